// round 12
// baseline (speedup 1.0000x reference)
#include <cuda_runtime.h>
#include <cuda_fp16.h>
#include <math.h>

// Problem constants
constexpr int TT = 12;
constexpr int NN = 50000;
constexpr int FF = 32;
constexpr int HH = 64;
constexpr int EE = 1600000;
constexpr int ROWS = TT * NN;     // 600000
constexpr int NB = (NN + 1023) / 1024;   // 49 scan blocks

// ---------------- static device scratch (zero-initialized at load) ---------
__device__ int     g_degi[NN];
__device__ int     g_cursor[NN];
__device__ float   g_dinv[NN];
__device__ float   g_invdeg[NN];
__device__ int     g_rowptr[NN + 1];     // local (per-scan-block) prefix
__device__ int     g_bsum[64];
__device__ int     g_boff[64];
__device__ unsigned int g_done0;
__device__ unsigned int g_epku[EE];                        // packed src:16 | w:fp16
__device__ uint4   g_xhu4[(size_t)ROWS * FF / 8];          // 38.4 MB x fp16
__device__ uint4   g_h1u4[(size_t)ROWS * HH / 8];          // 76.8 MB h1 fp16
__device__ uint4   g_p2u4[(size_t)ROWS * HH / 8];          // 76.8 MB P2 fp16

#define H1H  ((__half*)g_h1u4)
#define P2H  ((__half*)g_p2u4)

// ---------------- helpers ---------------------------------------------------
union F2U { float2 f; unsigned long long u; };
__device__ __forceinline__ float2 ffma2(float2 a, float2 b, float2 c) {
    F2U A, B, C, D; A.f = a; B.f = b; C.f = c;
    asm("fma.rn.f32x2 %0, %1, %2, %3;" : "=l"(D.u) : "l"(A.u), "l"(B.u), "l"(C.u));
    return D.f;
}
__device__ __forceinline__ float2 h2f2(unsigned int u) {
    __half2 h = *reinterpret_cast<const __half2*>(&u);
    return __half22float2(h);
}
__device__ __forceinline__ unsigned int pack2h(float a, float b) {
    __half2 h = __floats2half2_rn(a, b);
    return *reinterpret_cast<unsigned int*>(&h);
}
// fast activations (MUFU-based, ~1e-6 rel err; overflow-safe)
__device__ __forceinline__ float sigf(float x) {
    return __frcp_rn(1.f + __expf(-x));
}
__device__ __forceinline__ float tanhf_fast(float x) {
    float a = fabsf(x);
    float t = __expf(-2.f * a);
    float r = (1.f - t) * __frcp_rn(1.f + t);
    return copysignf(r, x);
}

// m16n8k16 fp16 MMA, fp32 accumulate (A row-major, B col-major)
__device__ __forceinline__ void mma16816(float* c, const unsigned int* a, const unsigned int* b) {
    asm volatile(
        "mma.sync.aligned.m16n8k16.row.col.f32.f16.f16.f32 "
        "{%0,%1,%2,%3}, {%4,%5,%6,%7}, {%8,%9}, {%0,%1,%2,%3};\n"
        : "+f"(c[0]), "+f"(c[1]), "+f"(c[2]), "+f"(c[3])
        : "r"(a[0]), "r"(a[1]), "r"(a[2]), "r"(a[3]), "r"(b[0]), "r"(b[1]));
}

// ---------------- preprocessing --------------------------------------------
__global__ __launch_bounds__(256) void k_countcvt(const int* __restrict__ dst, int E,
                                                  const float4* __restrict__ x4) {
    unsigned int i = blockIdx.x * blockDim.x + threadIdx.x;
    if (i < (unsigned int)E) atomicAdd(&g_degi[dst[i]], 1);
    if (i < (unsigned int)(ROWS * FF / 4)) {
        float4 v = x4[i];
        ((uint2*)g_xhu4)[i] = make_uint2(pack2h(v.x, v.y), pack2h(v.z, v.w));
    }
}

// stage 1 + stage 2 fused (last-done block performs the 64-entry scan)
__global__ void k_pre12() {
    __shared__ int wsum[32];
    __shared__ unsigned int amLast;
    int b = blockIdx.x, tid = threadIdx.x, lane = tid & 31, wid = tid >> 5;
    int idx = b * 1024 + tid;
    int v = (idx < NN) ? g_degi[idx] : 0;
    int x = v;
    #pragma unroll
    for (int o = 1; o < 32; o <<= 1) {
        int y = __shfl_up_sync(0xffffffffu, x, o);
        if (lane >= o) x += y;
    }
    if (lane == 31) wsum[wid] = x;
    __syncthreads();
    if (wid == 0) {
        int w = wsum[lane];
        int xw = w;
        #pragma unroll
        for (int o = 1; o < 32; o <<= 1) {
            int y = __shfl_up_sync(0xffffffffu, xw, o);
            if (lane >= o) xw += y;
        }
        wsum[lane] = xw - w;
    }
    __syncthreads();
    int excl = wsum[wid] + x - v;
    if (idx < NN) {
        g_rowptr[idx] = excl;
        float deg = (float)v + 1.0f;
        g_dinv[idx] = rsqrtf(deg);
        g_invdeg[idx] = 1.0f / deg;
    }
    if (tid == 1023) g_bsum[b] = excl + v;

    // last-done block performs stage 2
    __threadfence();
    if (tid == 0) amLast = (atomicAdd(&g_done0, 1) == NB - 1) ? 1u : 0u;
    __syncthreads();
    if (amLast) {
        if (tid == 0) g_done0 = 0;   // reset for next call
        if (wid == 0) {
            int l = lane;
            int a = (l < NB) ? g_bsum[l] : 0;
            int xa = a;
            #pragma unroll
            for (int o = 1; o < 32; o <<= 1) {
                int y = __shfl_up_sync(0xffffffffu, xa, o);
                if (l >= o) xa += y;
            }
            int totalA = __shfl_sync(0xffffffffu, xa, 31);
            int b2 = (l + 32 < NB) ? g_bsum[l + 32] : 0;
            int xb = b2;
            #pragma unroll
            for (int o = 1; o < 32; o <<= 1) {
                int y = __shfl_up_sync(0xffffffffu, xb, o);
                if (l >= o) xb += y;
            }
            g_boff[l] = xa - a;
            if (l + 32 < NB + 1) g_boff[l + 32] = totalA + xb - b2;
            if (l == 0) g_rowptr[NN] = g_bsum[NB - 1];
        }
    }
}

__global__ void k_fill(const int* __restrict__ src, const int* __restrict__ dst, int E) {
    int e = blockIdx.x * blockDim.x + threadIdx.x;
    int half = (E + 1) >> 1;
    int s0 = -1, d0 = 0, s1 = -1, d1 = 0;
    if (e < half) {
        s0 = src[e]; d0 = dst[e];
        int e1 = e + half;
        if (e1 < E) { s1 = src[e1]; d1 = dst[e1]; }
    }
    if (s0 >= 0) {
        float w = g_dinv[s0] * g_dinv[d0];
        int pos = g_rowptr[d0] + g_boff[d0 >> 10] + atomicAdd(&g_cursor[d0], 1);
        unsigned short ws = __half_as_ushort(__float2half_rn(w));
        g_epku[pos] = (unsigned int)s0 | ((unsigned int)ws << 16);
    }
    if (s1 >= 0) {
        float w = g_dinv[s1] * g_dinv[d1];
        int pos = g_rowptr[d1] + g_boff[d1 >> 10] + atomicAdd(&g_cursor[d1], 1);
        unsigned short ws = __half_as_ushort(__float2half_rn(w));
        g_epku[pos] = (unsigned int)s1 | ((unsigned int)ws << 16);
    }
}

__device__ __forceinline__ void decode_edge(unsigned int e, int& ss, float& ww) {
    ss = (int)(e & 0xFFFFu);
    ww = __half2float(__ushort_as_half((unsigned short)(e >> 16)));
}

// ---------------- fused agg32 + gemm1: h1 = relu((Ahat x) @ W1 + b1) --------
__global__ __launch_bounds__(256) void k_agg32f(const float* __restrict__ W,
                                                const float* __restrict__ b) {
    __shared__ unsigned int Wf[2 * 8 * 32 * 2];      // 4 KB  W1 B-frags
    __shared__ float2 Bf[8 * 32];                    // 2 KB  b1 frags
    __shared__ unsigned int Arows[8][16][16];        // 8 KB
    int tid = threadIdx.x;
    for (int i = tid; i < 2 * 8 * 32; i += 256) {
        int lane = i & 31, nt = (i >> 5) & 7, kt = i >> 8;
        int gq = lane >> 2, tq = lane & 3;
        int n = nt * 8 + gq, ks = kt * 16 + tq * 2;
        Wf[i * 2 + 0] = pack2h(W[ks * 64 + n], W[(ks + 1) * 64 + n]);
        Wf[i * 2 + 1] = pack2h(W[(ks + 8) * 64 + n], W[(ks + 9) * 64 + n]);
    }
    for (int i = tid; i < 8 * 32; i += 256) {
        int lane = i & 31, nt = i >> 5, tq = lane & 3;
        Bf[i] = make_float2(b[nt * 8 + tq * 2], b[nt * 8 + tq * 2 + 1]);
    }
    __syncthreads();

    int lane = tid & 31, wid = tid >> 5;
    int c = blockIdx.y;                              // t-chunk 0..2
    int quad = blockIdx.x * 8 + wid;
    if (quad >= NN / 4) return;
    int n0 = quad * 4;
    int g = lane >> 2, sub = lane & 3;
    const uint4* __restrict__ x4 = g_xhu4 + (size_t)(c * 4) * NN * 4 + sub;

    for (int r = 0; r < 4; r++) {
        int n = n0 + r;
        int r0 = g_rowptr[n] + g_boff[n >> 10];
        int r1 = g_rowptr[n + 1] + g_boff[(n + 1) >> 10];
        float2 acc[4][4];
        #pragma unroll
        for (int t = 0; t < 4; t++)
            #pragma unroll
            for (int j = 0; j < 4; j++) acc[t][j] = make_float2(0.f, 0.f);
        unsigned int ep = (r0 + lane < r1) ? g_epku[r0 + lane] : 0u;
        for (int tile = r0; tile < r1; tile += 32) {
            unsigned int epc = ep;
            int nxt = tile + 32;
            if (nxt < r1) ep = (nxt + lane < r1) ? g_epku[nxt + lane] : 0u;
            int nb = r1 - tile; if (nb > 32) nb = 32;
            for (int bb = 0; bb * 8 < nb; bb++) {
                unsigned int e = __shfl_sync(0xffffffffu, epc, bb * 8 + g);
                int ss; float ww; decode_edge(e, ss, ww);
                float2 w2 = make_float2(ww, ww);
                const uint4* p = x4 + (size_t)ss * 4;
                #pragma unroll
                for (int t = 0; t < 4; t++) {
                    uint4 v = p[(size_t)t * (NN * 4)];
                    acc[t][0] = ffma2(w2, h2f2(v.x), acc[t][0]);
                    acc[t][1] = ffma2(w2, h2f2(v.y), acc[t][1]);
                    acc[t][2] = ffma2(w2, h2f2(v.z), acc[t][2]);
                    acc[t][3] = ffma2(w2, h2f2(v.w), acc[t][3]);
                }
            }
        }
        if (g == 0) {   // self-loop
            float id = g_invdeg[n];
            float2 w2 = make_float2(id, id);
            const uint4* p = x4 + (size_t)n * 4;
            #pragma unroll
            for (int t = 0; t < 4; t++) {
                uint4 v = p[(size_t)t * (NN * 4)];
                acc[t][0] = ffma2(w2, h2f2(v.x), acc[t][0]);
                acc[t][1] = ffma2(w2, h2f2(v.y), acc[t][1]);
                acc[t][2] = ffma2(w2, h2f2(v.z), acc[t][2]);
                acc[t][3] = ffma2(w2, h2f2(v.w), acc[t][3]);
            }
        }
        #pragma unroll
        for (int t = 0; t < 4; t++) {
            #pragma unroll
            for (int j = 0; j < 4; j++) {
                float2 a = acc[t][j];
                #pragma unroll
                for (int off = 4; off <= 16; off <<= 1) {
                    a.x += __shfl_xor_sync(0xffffffffu, a.x, off);
                    a.y += __shfl_xor_sync(0xffffffffu, a.y, off);
                }
                if (g == t) Arows[wid][t * 4 + r][sub * 4 + j] = pack2h(a.x, a.y);
            }
        }
    }
    __syncwarp();

    int gq = lane >> 2, tq = lane & 3;
    unsigned int A[2][4];
    #pragma unroll
    for (int kt = 0; kt < 2; kt++) {
        A[kt][0] = Arows[wid][gq][kt * 8 + tq];
        A[kt][1] = Arows[wid][gq + 8][kt * 8 + tq];
        A[kt][2] = Arows[wid][gq][kt * 8 + tq + 4];
        A[kt][3] = Arows[wid][gq + 8][kt * 8 + tq + 4];
    }
    float cc[8][4];
    #pragma unroll
    for (int nt = 0; nt < 8; nt++) {
        float2 bb = Bf[nt * 32 + lane];
        cc[nt][0] = bb.x; cc[nt][1] = bb.y; cc[nt][2] = bb.x; cc[nt][3] = bb.y;
    }
    #pragma unroll
    for (int kt = 0; kt < 2; kt++)
        #pragma unroll
        for (int nt = 0; nt < 8; nt++)
            mma16816(cc[nt], A[kt], &Wf[((kt * 8 + nt) * 32 + lane) * 2]);
    int t0 = gq >> 2, ri = gq & 3;
    unsigned int* o0 = (unsigned int*)(H1H + ((size_t)(c * 4 + t0) * NN + n0 + ri) * 64);
    unsigned int* o8 = (unsigned int*)(H1H + ((size_t)(c * 4 + t0 + 2) * NN + n0 + ri) * 64);
    #pragma unroll
    for (int nt = 0; nt < 8; nt++) {
        o0[nt * 4 + tq] = pack2h(fmaxf(cc[nt][0], 0.f), fmaxf(cc[nt][1], 0.f));
        o8[nt * 4 + tq] = pack2h(fmaxf(cc[nt][2], 0.f), fmaxf(cc[nt][3], 0.f));
    }
}

// ---------------- aggregation layer 2: fp16 in/out, 2 t per slice -----------
__global__ __launch_bounds__(256) void k_agg64() {
    int lane = threadIdx.x & 31;
    int n = blockIdx.x * 8 + (threadIdx.x >> 5);
    if (n >= NN) return;
    int c = blockIdx.y;                                  // 0..5
    int g = lane >> 3, sub = lane & 7;
    int r0 = g_rowptr[n] + g_boff[n >> 10];
    int r1 = g_rowptr[n + 1] + g_boff[(n + 1) >> 10];
    const uint4* __restrict__ hb = g_h1u4 + (size_t)(c * 2) * NN * 8 + sub;
    float2 acc[2][4];
    #pragma unroll
    for (int t = 0; t < 2; t++)
        #pragma unroll
        for (int j = 0; j < 4; j++) acc[t][j] = make_float2(0.f, 0.f);
    unsigned int ep = (r0 + lane < r1) ? g_epku[r0 + lane] : 0u;
    for (int tile = r0; tile < r1; tile += 32) {
        unsigned int epc = ep;
        int nxt = tile + 32;
        if (nxt < r1) ep = (nxt + lane < r1) ? g_epku[nxt + lane] : 0u;
        int nb = r1 - tile; if (nb > 32) nb = 32;
        for (int b = 0; b * 4 < nb; b++) {
            unsigned int e = __shfl_sync(0xffffffffu, epc, b * 4 + g);
            int ss; float ww; decode_edge(e, ss, ww);
            float2 w2 = make_float2(ww, ww);
            const uint4* p = hb + (size_t)ss * 8;
            #pragma unroll
            for (int t = 0; t < 2; t++) {
                uint4 hv = p[(size_t)t * (NN * 8)];
                acc[t][0] = ffma2(w2, h2f2(hv.x), acc[t][0]);
                acc[t][1] = ffma2(w2, h2f2(hv.y), acc[t][1]);
                acc[t][2] = ffma2(w2, h2f2(hv.z), acc[t][2]);
                acc[t][3] = ffma2(w2, h2f2(hv.w), acc[t][3]);
            }
        }
    }
    if (g == 0) {
        float id = g_invdeg[n];
        float2 w2 = make_float2(id, id);
        const uint4* p = hb + (size_t)n * 8;
        #pragma unroll
        for (int t = 0; t < 2; t++) {
            uint4 hv = p[(size_t)t * (NN * 8)];
            acc[t][0] = ffma2(w2, h2f2(hv.x), acc[t][0]);
            acc[t][1] = ffma2(w2, h2f2(hv.y), acc[t][1]);
            acc[t][2] = ffma2(w2, h2f2(hv.z), acc[t][2]);
            acc[t][3] = ffma2(w2, h2f2(hv.w), acc[t][3]);
        }
    }
    #pragma unroll
    for (int t = 0; t < 2; t++) {
        #pragma unroll
        for (int j = 0; j < 4; j++) {
            float2 a = acc[t][j];
            #pragma unroll
            for (int off = 8; off <= 16; off <<= 1) {
                a.x += __shfl_xor_sync(0xffffffffu, a.x, off);
                a.y += __shfl_xor_sync(0xffffffffu, a.y, off);
            }
            acc[t][j] = a;
        }
        if (g == t) {
            uint4 pk;
            pk.x = pack2h(acc[t][0].x, acc[t][0].y);
            pk.y = pack2h(acc[t][1].x, acc[t][1].y);
            pk.z = pack2h(acc[t][2].x, acc[t][2].y);
            pk.w = pack2h(acc[t][3].x, acc[t][3].y);
            g_p2u4[((size_t)(c * 2 + t) * NN + n) * 8 + sub] = pk;
        }
    }
}

// ---------------- fused HMMA: h2+gi+GRU+classifier --------------------------
// B-frag tables laid out [nt][lane][kt] so 4 ktiles load as 2x LDS.128.
__global__ __launch_bounds__(256) void k_fused(const float* __restrict__ W2,
                                               const float* __restrict__ b2,
                                               const float* __restrict__ Wih,
                                               const float* __restrict__ bih,
                                               const float* __restrict__ Whh,
                                               const float* __restrict__ bhh,
                                               const float* __restrict__ Wc1,
                                               const float* __restrict__ bc1,
                                               const float* __restrict__ Wc2,
                                               const float* __restrict__ bc2,
                                               float* __restrict__ out) {
    extern __shared__ unsigned int smu[];
    unsigned int* W2f  = smu;                  // [0,2048)
    unsigned int* Wihf = smu + 2048;           // [2048,8192)
    unsigned int* Whhf = smu + 8192;           // [8192,14336)
    float2* B2f = (float2*)(smu + 14336);      // [14336,14848)
    float2* Brz = (float2*)(smu + 14848);      // [14848,15872)
    float2* Bin = (float2*)(smu + 15872);      // [15872,16384)
    float2* Bhn = (float2*)(smu + 16384);      // [16384,16896)
    unsigned int* Wc1f = smu + 16896;          // [16896,17920)
    float2* Bc1f = (float2*)(smu + 17920);     // [17920,18176)
    float* w2s = (float*)(smu + 18176);        // [18176,18208)
    int tid = threadIdx.x;

    int gid = blockIdx.x * 256 + tid;
    if (gid < NN) { g_degi[gid] = 0; g_cursor[gid] = 0; }

    // W2: [nt 0..7][lane][kt 0..3]
    for (int i = tid; i < 1024; i += 256) {
        int nt = i >> 7, lane = (i >> 2) & 31, kt = i & 3;
        int gq = lane >> 2, tq = lane & 3;
        int n = nt * 8 + gq, ks = kt * 16 + tq * 2;
        W2f[i * 2 + 0] = pack2h(W2[ks * 64 + n], W2[(ks + 1) * 64 + n]);
        W2f[i * 2 + 1] = pack2h(W2[(ks + 8) * 64 + n], W2[(ks + 9) * 64 + n]);
    }
    // Wih / Whh: [nt 0..23][lane][kt 0..3]
    for (int i = tid; i < 3072; i += 256) {
        int nt = i >> 7, lane = (i >> 2) & 31, kt = i & 3;
        int gq = lane >> 2, tq = lane & 3;
        int gcol = nt * 8 + gq, ks = kt * 16 + tq * 2;
        Wihf[i * 2 + 0] = pack2h(Wih[gcol * 64 + ks], Wih[gcol * 64 + ks + 1]);
        Wihf[i * 2 + 1] = pack2h(Wih[gcol * 64 + ks + 8], Wih[gcol * 64 + ks + 9]);
        Whhf[i * 2 + 0] = pack2h(Whh[gcol * 64 + ks], Whh[gcol * 64 + ks + 1]);
        Whhf[i * 2 + 1] = pack2h(Whh[gcol * 64 + ks + 8], Whh[gcol * 64 + ks + 9]);
    }
    // Wc1: [nt 0..3][lane][kt 0..3]
    for (int i = tid; i < 512; i += 256) {
        int nt = i >> 7, lane = (i >> 2) & 31, kt = i & 3;
        int gq = lane >> 2, tq = lane & 3;
        int n = nt * 8 + gq, ks = kt * 16 + tq * 2;
        Wc1f[i * 2 + 0] = pack2h(Wc1[ks * 32 + n], Wc1[(ks + 1) * 32 + n]);
        Wc1f[i * 2 + 1] = pack2h(Wc1[(ks + 8) * 32 + n], Wc1[(ks + 9) * 32 + n]);
    }
    for (int i = tid; i < 8 * 32; i += 256) {
        int lane = i & 31, nt = i >> 5, tq = lane & 3;
        B2f[i] = make_float2(b2[nt * 8 + tq * 2], b2[nt * 8 + tq * 2 + 1]);
        Bin[i] = make_float2(bih[128 + nt * 8 + tq * 2], bih[128 + nt * 8 + tq * 2 + 1]);
        Bhn[i] = make_float2(bhh[128 + nt * 8 + tq * 2], bhh[128 + nt * 8 + tq * 2 + 1]);
    }
    for (int i = tid; i < 16 * 32; i += 256) {
        int lane = i & 31, nt = i >> 5, tq = lane & 3;
        int k0 = nt * 8 + tq * 2;
        Brz[i] = make_float2(bih[k0] + bhh[k0], bih[k0 + 1] + bhh[k0 + 1]);
    }
    for (int i = tid; i < 4 * 32; i += 256) {
        int lane = i & 31, nt = i >> 5, tq = lane & 3;
        Bc1f[i] = make_float2(bc1[nt * 8 + tq * 2], bc1[nt * 8 + tq * 2 + 1]);
    }
    if (tid < 32) w2s[tid] = Wc2[tid];
    __syncthreads();

    int lane = tid & 31;
    int tile = blockIdx.x * 8 + (tid >> 5);
    if (tile >= NN / 16) return;
    int row0 = tile * 16;
    int gq = lane >> 2, tq = lane & 3;

    float hc[8][4];
    #pragma unroll
    for (int nt = 0; nt < 8; nt++)
        #pragma unroll
        for (int j = 0; j < 4; j++) hc[nt][j] = 0.f;

    for (int t = 0; t < TT; t++) {
        float dall[24][4];
        #pragma unroll
        for (int nt = 0; nt < 16; nt++) {
            float2 bb = Brz[nt * 32 + lane];
            dall[nt][0] = bb.x; dall[nt][1] = bb.y; dall[nt][2] = bb.x; dall[nt][3] = bb.y;
        }
        #pragma unroll
        for (int nt = 0; nt < 8; nt++) {
            float2 bb = Bhn[nt * 32 + lane];
            dall[16 + nt][0] = bb.x; dall[16 + nt][1] = bb.y;
            dall[16 + nt][2] = bb.x; dall[16 + nt][3] = bb.y;
        }
        if (t) {
            unsigned int Ah[4][4];
            #pragma unroll
            for (int kt = 0; kt < 4; kt++) {
                Ah[kt][0] = pack2h(hc[2 * kt][0], hc[2 * kt][1]);
                Ah[kt][1] = pack2h(hc[2 * kt][2], hc[2 * kt][3]);
                Ah[kt][2] = pack2h(hc[2 * kt + 1][0], hc[2 * kt + 1][1]);
                Ah[kt][3] = pack2h(hc[2 * kt + 1][2], hc[2 * kt + 1][3]);
            }
            #pragma unroll
            for (int nt = 0; nt < 24; nt++) {
                const uint4* bp = (const uint4*)&Whhf[(nt * 32 + lane) * 8];
                uint4 b01 = bp[0], b23 = bp[1];
                mma16816(dall[nt], Ah[0], &b01.x);
                mma16816(dall[nt], Ah[1], &b01.z);
                mma16816(dall[nt], Ah[2], &b23.x);
                mma16816(dall[nt], Ah[3], &b23.z);
            }
        }
        unsigned int A[4][4];
        {
            const unsigned int* base0 = (const unsigned int*)(P2H + ((size_t)t * NN + row0 + gq) * 64);
            const unsigned int* base8 = base0 + 8 * 32;
            #pragma unroll
            for (int kt = 0; kt < 4; kt++) {
                A[kt][0] = base0[kt * 8 + tq];
                A[kt][1] = base8[kt * 8 + tq];
                A[kt][2] = base0[kt * 8 + tq + 4];
                A[kt][3] = base8[kt * 8 + tq + 4];
            }
        }
        float c[8][4];
        #pragma unroll
        for (int nt = 0; nt < 8; nt++) {
            float2 bb = B2f[nt * 32 + lane];
            c[nt][0] = bb.x; c[nt][1] = bb.y; c[nt][2] = bb.x; c[nt][3] = bb.y;
        }
        #pragma unroll
        for (int nt = 0; nt < 8; nt++) {
            const uint4* bp = (const uint4*)&W2f[(nt * 32 + lane) * 8];
            uint4 b01 = bp[0], b23 = bp[1];
            mma16816(c[nt], A[0], &b01.x);
            mma16816(c[nt], A[1], &b01.z);
            mma16816(c[nt], A[2], &b23.x);
            mma16816(c[nt], A[3], &b23.z);
        }
        unsigned int A2[4][4];
        #pragma unroll
        for (int kt = 0; kt < 4; kt++) {
            A2[kt][0] = pack2h(fmaxf(c[2 * kt][0], 0.f), fmaxf(c[2 * kt][1], 0.f));
            A2[kt][1] = pack2h(fmaxf(c[2 * kt][2], 0.f), fmaxf(c[2 * kt][3], 0.f));
            A2[kt][2] = pack2h(fmaxf(c[2 * kt + 1][0], 0.f), fmaxf(c[2 * kt + 1][1], 0.f));
            A2[kt][3] = pack2h(fmaxf(c[2 * kt + 1][2], 0.f), fmaxf(c[2 * kt + 1][3], 0.f));
        }
        float din[8][4];
        #pragma unroll
        for (int nt = 0; nt < 8; nt++) {
            float2 bb = Bin[nt * 32 + lane];
            din[nt][0] = bb.x; din[nt][1] = bb.y; din[nt][2] = bb.x; din[nt][3] = bb.y;
        }
        #pragma unroll
        for (int nt = 0; nt < 16; nt++) {
            const uint4* bp = (const uint4*)&Wihf[(nt * 32 + lane) * 8];
            uint4 b01 = bp[0], b23 = bp[1];
            mma16816(dall[nt], A2[0], &b01.x);
            mma16816(dall[nt], A2[1], &b01.z);
            mma16816(dall[nt], A2[2], &b23.x);
            mma16816(dall[nt], A2[3], &b23.z);
        }
        #pragma unroll
        for (int nt = 0; nt < 8; nt++) {
            const uint4* bp = (const uint4*)&Wihf[((16 + nt) * 32 + lane) * 8];
            uint4 b01 = bp[0], b23 = bp[1];
            mma16816(din[nt], A2[0], &b01.x);
            mma16816(din[nt], A2[1], &b01.z);
            mma16816(din[nt], A2[2], &b23.x);
            mma16816(din[nt], A2[3], &b23.z);
        }
        #pragma unroll
        for (int nt = 0; nt < 8; nt++) {
            #pragma unroll
            for (int j = 0; j < 4; j++) {
                float r = sigf(dall[nt][j]);
                float z = sigf(dall[nt + 8][j]);
                float n = tanhf_fast(din[nt][j] + r * dall[nt + 16][j]);
                hc[nt][j] = (1.f - z) * n + z * hc[nt][j];
            }
        }
    }

    // ---- classifier
    unsigned int Ah[4][4];
    #pragma unroll
    for (int kt = 0; kt < 4; kt++) {
        Ah[kt][0] = pack2h(hc[2 * kt][0], hc[2 * kt][1]);
        Ah[kt][1] = pack2h(hc[2 * kt][2], hc[2 * kt][3]);
        Ah[kt][2] = pack2h(hc[2 * kt + 1][0], hc[2 * kt + 1][1]);
        Ah[kt][3] = pack2h(hc[2 * kt + 1][2], hc[2 * kt + 1][3]);
    }
    float hid[4][4];
    #pragma unroll
    for (int nt = 0; nt < 4; nt++) {
        float2 bb = Bc1f[nt * 32 + lane];
        hid[nt][0] = bb.x; hid[nt][1] = bb.y; hid[nt][2] = bb.x; hid[nt][3] = bb.y;
    }
    #pragma unroll
    for (int nt = 0; nt < 4; nt++) {
        const uint4* bp = (const uint4*)&Wc1f[(nt * 32 + lane) * 8];
        uint4 b01 = bp[0], b23 = bp[1];
        mma16816(hid[nt], Ah[0], &b01.x);
        mma16816(hid[nt], Ah[1], &b01.z);
        mma16816(hid[nt], Ah[2], &b23.x);
        mma16816(hid[nt], Ah[3], &b23.z);
    }
    float p0 = 0.f, p8 = 0.f;
    #pragma unroll
    for (int nt = 0; nt < 4; nt++) {
        float w0 = w2s[nt * 8 + tq * 2], w1 = w2s[nt * 8 + tq * 2 + 1];
        p0 += fmaxf(hid[nt][0], 0.f) * w0 + fmaxf(hid[nt][1], 0.f) * w1;
        p8 += fmaxf(hid[nt][2], 0.f) * w0 + fmaxf(hid[nt][3], 0.f) * w1;
    }
    p0 += __shfl_xor_sync(0xffffffffu, p0, 1);
    p0 += __shfl_xor_sync(0xffffffffu, p0, 2);
    p8 += __shfl_xor_sync(0xffffffffu, p8, 1);
    p8 += __shfl_xor_sync(0xffffffffu, p8, 2);
    if (tq == 0) {
        float bv = bc2[0];
        out[row0 + gq] = p0 + bv;
        out[row0 + gq + 8] = p8 + bv;
    }
}

// ---------------- launch ----------------------------------------------------
extern "C" void kernel_launch(void* const* d_in, const int* in_sizes, int n_in,
                              void* d_out, int out_size) {
    const float* x   = (const float*)d_in[0];
    const int*   ei  = (const int*)d_in[1];
    const float* W1  = (const float*)d_in[2];
    const float* b1  = (const float*)d_in[3];
    const float* W2  = (const float*)d_in[4];
    const float* b2  = (const float*)d_in[5];
    const float* Wih = (const float*)d_in[6];
    const float* Whh = (const float*)d_in[7];
    const float* bih = (const float*)d_in[8];
    const float* bhh = (const float*)d_in[9];
    const float* Wc1 = (const float*)d_in[10];
    const float* bc1 = (const float*)d_in[11];
    const float* Wc2 = (const float*)d_in[12];
    const float* bc2 = (const float*)d_in[13];
    float* out = (float*)d_out;

    int E = in_sizes[1] / 2;
    const int* src = ei;
    const int* dst = ei + E;

    cudaFuncSetAttribute(k_fused, cudaFuncAttributeMaxDynamicSharedMemorySize, 73728);

    // preprocessing (3 launches): count+cvt, fused scan, CSR fill
    k_countcvt<<<(ROWS * FF / 4 + 255) / 256, 256>>>(dst, E, (const float4*)x);
    k_pre12<<<NB, 1024>>>();
    k_fill<<<((E + 1) / 2 + 255) / 256, 256>>>(src, dst, E);

    // fused agg32 + gemm1: h1 = relu((Ahat x) @ W1 + b1) -> fp16 H1H
    k_agg32f<<<dim3((NN / 4 + 7) / 8, 3), 256>>>(W1, b1);

    // layer 2: P2 = Ahat * h1 (6 chunks of 2 t) -> fp16 P2H
    k_agg64<<<dim3(NN / 8, 6), 256>>>();

    // fused HMMA: h2 + gi + 12-step GRU + classifier -> out
    k_fused<<<(NN / 16 + 7) / 8, 256, 73728>>>(W2, b2, Wih, bih, Whh, bhh,
                                               Wc1, bc1, Wc2, bc2, out);
}

// round 13
// speedup vs baseline: 1.0582x; 1.0582x over previous
#include <cuda_runtime.h>
#include <cuda_fp16.h>
#include <math.h>

// Problem constants
constexpr int TT = 12;
constexpr int NN = 50000;
constexpr int FF = 32;
constexpr int HH = 64;
constexpr int EE = 1600000;
constexpr int ROWS = TT * NN;     // 600000
constexpr int NB = (NN + 1023) / 1024;   // 49 scan blocks

// ---------------- static device scratch (zero-initialized at load) ---------
__device__ int     g_degi[NN];
__device__ int     g_cursor[NN];
__device__ float   g_dinv[NN];
__device__ float   g_invdeg[NN];
__device__ int     g_rowptr[NN + 1];     // local (per-scan-block) prefix
__device__ int     g_bsum[64];
__device__ int     g_boff[64];
__device__ unsigned int g_done0;
__device__ unsigned int g_epku[EE];                        // packed src:16 | w:fp16
__device__ uint4   g_xhu4[(size_t)ROWS * FF / 8];          // 38.4 MB x fp16
__device__ uint4   g_p1u4[(size_t)ROWS * FF / 8];          // 38.4 MB P1 fp16
__device__ uint4   g_h1u4[(size_t)ROWS * HH / 8];          // 76.8 MB h1 fp16
__device__ uint4   g_p2u4[(size_t)ROWS * HH / 8];          // 76.8 MB P2 fp16

#define P1H  ((__half*)g_p1u4)
#define H1H  ((__half*)g_h1u4)
#define P2H  ((__half*)g_p2u4)

// ---------------- helpers ---------------------------------------------------
union F2U { float2 f; unsigned long long u; };
__device__ __forceinline__ float2 ffma2(float2 a, float2 b, float2 c) {
    F2U A, B, C, D; A.f = a; B.f = b; C.f = c;
    asm("fma.rn.f32x2 %0, %1, %2, %3;" : "=l"(D.u) : "l"(A.u), "l"(B.u), "l"(C.u));
    return D.f;
}
__device__ __forceinline__ float2 h2f2(unsigned int u) {
    __half2 h = *reinterpret_cast<const __half2*>(&u);
    return __half22float2(h);
}
__device__ __forceinline__ unsigned int pack2h(float a, float b) {
    __half2 h = __floats2half2_rn(a, b);
    return *reinterpret_cast<unsigned int*>(&h);
}
// fast activations (MUFU-based, ~1e-6 rel err; overflow-safe)
__device__ __forceinline__ float sigf(float x) {
    return __frcp_rn(1.f + __expf(-x));
}
__device__ __forceinline__ float tanhf_fast(float x) {
    float a = fabsf(x);
    float t = __expf(-2.f * a);
    float r = (1.f - t) * __frcp_rn(1.f + t);
    return copysignf(r, x);
}

// m16n8k16 fp16 MMA, fp32 accumulate (A row-major, B col-major)
__device__ __forceinline__ void mma16816(float* c, const unsigned int* a, const unsigned int* b) {
    asm volatile(
        "mma.sync.aligned.m16n8k16.row.col.f32.f16.f16.f32 "
        "{%0,%1,%2,%3}, {%4,%5,%6,%7}, {%8,%9}, {%0,%1,%2,%3};\n"
        : "+f"(c[0]), "+f"(c[1]), "+f"(c[2]), "+f"(c[3])
        : "r"(a[0]), "r"(a[1]), "r"(a[2]), "r"(a[3]), "r"(b[0]), "r"(b[1]));
}

// ---------------- preprocessing --------------------------------------------
__global__ __launch_bounds__(256) void k_countcvt(const int* __restrict__ dst, int E,
                                                  const float4* __restrict__ x4) {
    unsigned int i = blockIdx.x * blockDim.x + threadIdx.x;
    if (i < (unsigned int)E) atomicAdd(&g_degi[dst[i]], 1);
    if (i < (unsigned int)(ROWS * FF / 4)) {
        float4 v = x4[i];
        ((uint2*)g_xhu4)[i] = make_uint2(pack2h(v.x, v.y), pack2h(v.z, v.w));
    }
}

// stage 1 + stage 2 fused (last-done block performs the 64-entry scan)
__global__ void k_pre12() {
    __shared__ int wsum[32];
    __shared__ unsigned int amLast;
    int b = blockIdx.x, tid = threadIdx.x, lane = tid & 31, wid = tid >> 5;
    int idx = b * 1024 + tid;
    int v = (idx < NN) ? g_degi[idx] : 0;
    int x = v;
    #pragma unroll
    for (int o = 1; o < 32; o <<= 1) {
        int y = __shfl_up_sync(0xffffffffu, x, o);
        if (lane >= o) x += y;
    }
    if (lane == 31) wsum[wid] = x;
    __syncthreads();
    if (wid == 0) {
        int w = wsum[lane];
        int xw = w;
        #pragma unroll
        for (int o = 1; o < 32; o <<= 1) {
            int y = __shfl_up_sync(0xffffffffu, xw, o);
            if (lane >= o) xw += y;
        }
        wsum[lane] = xw - w;
    }
    __syncthreads();
    int excl = wsum[wid] + x - v;
    if (idx < NN) {
        g_rowptr[idx] = excl;
        float deg = (float)v + 1.0f;
        g_dinv[idx] = rsqrtf(deg);
        g_invdeg[idx] = 1.0f / deg;
    }
    if (tid == 1023) g_bsum[b] = excl + v;

    __threadfence();
    if (tid == 0) amLast = (atomicAdd(&g_done0, 1) == NB - 1) ? 1u : 0u;
    __syncthreads();
    if (amLast) {
        if (tid == 0) g_done0 = 0;
        if (wid == 0) {
            int l = lane;
            int a = (l < NB) ? g_bsum[l] : 0;
            int xa = a;
            #pragma unroll
            for (int o = 1; o < 32; o <<= 1) {
                int y = __shfl_up_sync(0xffffffffu, xa, o);
                if (l >= o) xa += y;
            }
            int totalA = __shfl_sync(0xffffffffu, xa, 31);
            int b2 = (l + 32 < NB) ? g_bsum[l + 32] : 0;
            int xb = b2;
            #pragma unroll
            for (int o = 1; o < 32; o <<= 1) {
                int y = __shfl_up_sync(0xffffffffu, xb, o);
                if (l >= o) xb += y;
            }
            g_boff[l] = xa - a;
            if (l + 32 < NB + 1) g_boff[l + 32] = totalA + xb - b2;
            if (l == 0) g_rowptr[NN] = g_bsum[NB - 1];
        }
    }
}

__global__ void k_fill(const int* __restrict__ src, const int* __restrict__ dst, int E) {
    int e = blockIdx.x * blockDim.x + threadIdx.x;
    int half = (E + 1) >> 1;
    int s0 = -1, d0 = 0, s1 = -1, d1 = 0;
    if (e < half) {
        s0 = src[e]; d0 = dst[e];
        int e1 = e + half;
        if (e1 < E) { s1 = src[e1]; d1 = dst[e1]; }
    }
    if (s0 >= 0) {
        float w = g_dinv[s0] * g_dinv[d0];
        int pos = g_rowptr[d0] + g_boff[d0 >> 10] + atomicAdd(&g_cursor[d0], 1);
        unsigned short ws = __half_as_ushort(__float2half_rn(w));
        g_epku[pos] = (unsigned int)s0 | ((unsigned int)ws << 16);
    }
    if (s1 >= 0) {
        float w = g_dinv[s1] * g_dinv[d1];
        int pos = g_rowptr[d1] + g_boff[d1 >> 10] + atomicAdd(&g_cursor[d1], 1);
        unsigned short ws = __half_as_ushort(__float2half_rn(w));
        g_epku[pos] = (unsigned int)s1 | ((unsigned int)ws << 16);
    }
}

__device__ __forceinline__ void decode_edge(unsigned int e, int& ss, float& ww) {
    ss = (int)(e & 0xFFFFu);
    ww = __half2float(__ushort_as_half((unsigned short)(e >> 16)));
}

// ---------------- aggregation layer 1: warp-per-node, fp16 gather -----------
// 8 groups of 4 lanes: group owns one edge; lane's uint4 = 8 fp16 features.
// P1 written fp16.
__global__ __launch_bounds__(256) void k_agg32() {
    int lane = threadIdx.x & 31;
    int n = blockIdx.x * 8 + (threadIdx.x >> 5);
    if (n >= NN) return;
    int c = blockIdx.y;                                  // 0..2
    int g = lane >> 2, sub = lane & 3;
    const uint4* __restrict__ x4 = g_xhu4 + (size_t)(c * 4) * NN * 4 + sub;
    int r0 = g_rowptr[n] + g_boff[n >> 10];
    int r1 = g_rowptr[n + 1] + g_boff[(n + 1) >> 10];
    float2 acc[4][4];
    #pragma unroll
    for (int t = 0; t < 4; t++)
        #pragma unroll
        for (int j = 0; j < 4; j++) acc[t][j] = make_float2(0.f, 0.f);
    unsigned int ep = (r0 + lane < r1) ? g_epku[r0 + lane] : 0u;
    for (int tile = r0; tile < r1; tile += 32) {
        unsigned int epc = ep;
        int nxt = tile + 32;
        if (nxt < r1) ep = (nxt + lane < r1) ? g_epku[nxt + lane] : 0u;
        int nb = r1 - tile; if (nb > 32) nb = 32;
        for (int b = 0; b * 8 < nb; b++) {
            unsigned int e = __shfl_sync(0xffffffffu, epc, b * 8 + g);
            int ss; float ww; decode_edge(e, ss, ww);
            float2 w2 = make_float2(ww, ww);
            const uint4* p = x4 + (size_t)ss * 4;
            #pragma unroll
            for (int t = 0; t < 4; t++) {
                uint4 v = p[(size_t)t * (NN * 4)];
                acc[t][0] = ffma2(w2, h2f2(v.x), acc[t][0]);
                acc[t][1] = ffma2(w2, h2f2(v.y), acc[t][1]);
                acc[t][2] = ffma2(w2, h2f2(v.z), acc[t][2]);
                acc[t][3] = ffma2(w2, h2f2(v.w), acc[t][3]);
            }
        }
    }
    if (g == 0) {   // self-loop, added once pre-reduction
        float id = g_invdeg[n];
        float2 w2 = make_float2(id, id);
        const uint4* p = x4 + (size_t)n * 4;
        #pragma unroll
        for (int t = 0; t < 4; t++) {
            uint4 v = p[(size_t)t * (NN * 4)];
            acc[t][0] = ffma2(w2, h2f2(v.x), acc[t][0]);
            acc[t][1] = ffma2(w2, h2f2(v.y), acc[t][1]);
            acc[t][2] = ffma2(w2, h2f2(v.z), acc[t][2]);
            acc[t][3] = ffma2(w2, h2f2(v.w), acc[t][3]);
        }
    }
    #pragma unroll
    for (int t = 0; t < 4; t++) {
        #pragma unroll
        for (int j = 0; j < 4; j++) {
            float2 a = acc[t][j];
            #pragma unroll
            for (int off = 4; off <= 16; off <<= 1) {
                a.x += __shfl_xor_sync(0xffffffffu, a.x, off);
                a.y += __shfl_xor_sync(0xffffffffu, a.y, off);
            }
            acc[t][j] = a;
        }
        if (g == t) {
            uint4 pk;
            pk.x = pack2h(acc[t][0].x, acc[t][0].y);
            pk.y = pack2h(acc[t][1].x, acc[t][1].y);
            pk.z = pack2h(acc[t][2].x, acc[t][2].y);
            pk.w = pack2h(acc[t][3].x, acc[t][3].y);
            g_p1u4[((size_t)(c * 4 + t) * NN + n) * 4 + sub] = pk;
        }
    }
}

// ---------------- HMMA dense layer 1: h1 = relu(P1 @ W1 + b1) -> fp16 -------
__global__ __launch_bounds__(256) void k_gemm1h(const float* __restrict__ W,
                                                const float* __restrict__ b) {
    __shared__ unsigned int Wf[2 * 8 * 32 * 2];   // 4 KB
    __shared__ float2 Bf[8 * 32];                 // 2 KB
    int tid = threadIdx.x;
    for (int i = tid; i < 2 * 8 * 32; i += 256) {
        int lane = i & 31, nt = (i >> 5) & 7, kt = i >> 8;
        int gq = lane >> 2, tq = lane & 3;
        int n = nt * 8 + gq, ks = kt * 16 + tq * 2;
        Wf[i * 2 + 0] = pack2h(W[ks * 64 + n], W[(ks + 1) * 64 + n]);
        Wf[i * 2 + 1] = pack2h(W[(ks + 8) * 64 + n], W[(ks + 9) * 64 + n]);
    }
    for (int i = tid; i < 8 * 32; i += 256) {
        int lane = i & 31, nt = i >> 5, tq = lane & 3;
        Bf[i] = make_float2(b[nt * 8 + tq * 2], b[nt * 8 + tq * 2 + 1]);
    }
    __syncthreads();
    int lane = tid & 31;
    int tile = blockIdx.x * 8 + (tid >> 5);
    if (tile >= ROWS / 16) return;
    int row0 = tile * 16;
    int gq = lane >> 2, tq = lane & 3;

    unsigned int A[2][4];
    const unsigned int* base0 = (const unsigned int*)(P1H + (size_t)(row0 + gq) * 32);
    const unsigned int* base8 = (const unsigned int*)(P1H + (size_t)(row0 + gq + 8) * 32);
    #pragma unroll
    for (int kt = 0; kt < 2; kt++) {
        A[kt][0] = base0[kt * 8 + tq];
        A[kt][1] = base8[kt * 8 + tq];
        A[kt][2] = base0[kt * 8 + tq + 4];
        A[kt][3] = base8[kt * 8 + tq + 4];
    }
    float c[8][4];
    #pragma unroll
    for (int nt = 0; nt < 8; nt++) {
        float2 bb = Bf[nt * 32 + lane];
        c[nt][0] = bb.x; c[nt][1] = bb.y; c[nt][2] = bb.x; c[nt][3] = bb.y;
    }
    #pragma unroll
    for (int kt = 0; kt < 2; kt++)
        #pragma unroll
        for (int nt = 0; nt < 8; nt++)
            mma16816(c[nt], A[kt], &Wf[((kt * 8 + nt) * 32 + lane) * 2]);
    unsigned int* o0 = (unsigned int*)(H1H + (size_t)(row0 + gq) * 64);
    unsigned int* o8 = (unsigned int*)(H1H + (size_t)(row0 + gq + 8) * 64);
    #pragma unroll
    for (int nt = 0; nt < 8; nt++) {
        o0[nt * 4 + tq] = pack2h(fmaxf(c[nt][0], 0.f), fmaxf(c[nt][1], 0.f));
        o8[nt * 4 + tq] = pack2h(fmaxf(c[nt][2], 0.f), fmaxf(c[nt][3], 0.f));
    }
}

// ---------------- aggregation layer 2: fp16 in/out, 2 t per slice -----------
__global__ __launch_bounds__(256) void k_agg64() {
    int lane = threadIdx.x & 31;
    int n = blockIdx.x * 8 + (threadIdx.x >> 5);
    if (n >= NN) return;
    int c = blockIdx.y;                                  // 0..5
    int g = lane >> 3, sub = lane & 7;
    int r0 = g_rowptr[n] + g_boff[n >> 10];
    int r1 = g_rowptr[n + 1] + g_boff[(n + 1) >> 10];
    const uint4* __restrict__ hb = g_h1u4 + (size_t)(c * 2) * NN * 8 + sub;
    float2 acc[2][4];
    #pragma unroll
    for (int t = 0; t < 2; t++)
        #pragma unroll
        for (int j = 0; j < 4; j++) acc[t][j] = make_float2(0.f, 0.f);
    unsigned int ep = (r0 + lane < r1) ? g_epku[r0 + lane] : 0u;
    for (int tile = r0; tile < r1; tile += 32) {
        unsigned int epc = ep;
        int nxt = tile + 32;
        if (nxt < r1) ep = (nxt + lane < r1) ? g_epku[nxt + lane] : 0u;
        int nb = r1 - tile; if (nb > 32) nb = 32;
        for (int b = 0; b * 4 < nb; b++) {
            unsigned int e = __shfl_sync(0xffffffffu, epc, b * 4 + g);
            int ss; float ww; decode_edge(e, ss, ww);
            float2 w2 = make_float2(ww, ww);
            const uint4* p = hb + (size_t)ss * 8;
            #pragma unroll
            for (int t = 0; t < 2; t++) {
                uint4 hv = p[(size_t)t * (NN * 8)];
                acc[t][0] = ffma2(w2, h2f2(hv.x), acc[t][0]);
                acc[t][1] = ffma2(w2, h2f2(hv.y), acc[t][1]);
                acc[t][2] = ffma2(w2, h2f2(hv.z), acc[t][2]);
                acc[t][3] = ffma2(w2, h2f2(hv.w), acc[t][3]);
            }
        }
    }
    if (g == 0) {
        float id = g_invdeg[n];
        float2 w2 = make_float2(id, id);
        const uint4* p = hb + (size_t)n * 8;
        #pragma unroll
        for (int t = 0; t < 2; t++) {
            uint4 hv = p[(size_t)t * (NN * 8)];
            acc[t][0] = ffma2(w2, h2f2(hv.x), acc[t][0]);
            acc[t][1] = ffma2(w2, h2f2(hv.y), acc[t][1]);
            acc[t][2] = ffma2(w2, h2f2(hv.z), acc[t][2]);
            acc[t][3] = ffma2(w2, h2f2(hv.w), acc[t][3]);
        }
    }
    #pragma unroll
    for (int t = 0; t < 2; t++) {
        #pragma unroll
        for (int j = 0; j < 4; j++) {
            float2 a = acc[t][j];
            #pragma unroll
            for (int off = 8; off <= 16; off <<= 1) {
                a.x += __shfl_xor_sync(0xffffffffu, a.x, off);
                a.y += __shfl_xor_sync(0xffffffffu, a.y, off);
            }
            acc[t][j] = a;
        }
        if (g == t) {
            uint4 pk;
            pk.x = pack2h(acc[t][0].x, acc[t][0].y);
            pk.y = pack2h(acc[t][1].x, acc[t][1].y);
            pk.z = pack2h(acc[t][2].x, acc[t][2].y);
            pk.w = pack2h(acc[t][3].x, acc[t][3].y);
            g_p2u4[((size_t)(c * 2 + t) * NN + n) * 8 + sub] = pk;
        }
    }
}

// ---------------- fused HMMA: h2+gi+GRU+classifier --------------------------
// B-frag layout: ((kt*NT+nt)*32+lane)*2 — lane-adjacent 8B LDS, conflict-free.
__global__ __launch_bounds__(256) void k_fused(const float* __restrict__ W2,
                                               const float* __restrict__ b2,
                                               const float* __restrict__ Wih,
                                               const float* __restrict__ bih,
                                               const float* __restrict__ Whh,
                                               const float* __restrict__ bhh,
                                               const float* __restrict__ Wc1,
                                               const float* __restrict__ bc1,
                                               const float* __restrict__ Wc2,
                                               const float* __restrict__ bc2,
                                               float* __restrict__ out) {
    extern __shared__ unsigned int smu[];
    unsigned int* W2f  = smu;                  // [0,2048)
    unsigned int* Wihf = smu + 2048;           // [2048,8192)
    unsigned int* Whhf = smu + 8192;           // [8192,14336)
    float2* B2f = (float2*)(smu + 14336);      // [14336,14848)
    float2* Brz = (float2*)(smu + 14848);      // [14848,15872)
    float2* Bin = (float2*)(smu + 15872);      // [15872,16384)
    float2* Bhn = (float2*)(smu + 16384);      // [16384,16896)
    unsigned int* Wc1f = smu + 16896;          // [16896,17920)
    float2* Bc1f = (float2*)(smu + 17920);     // [17920,18176)
    float* w2s = (float*)(smu + 18176);        // [18176,18208)
    int tid = threadIdx.x;

    int gid = blockIdx.x * 256 + tid;
    if (gid < NN) { g_degi[gid] = 0; g_cursor[gid] = 0; }

    for (int i = tid; i < 4 * 8 * 32; i += 256) {
        int lane = i & 31, nt = (i >> 5) & 7, kt = i >> 8;
        int gq = lane >> 2, tq = lane & 3;
        int n = nt * 8 + gq, ks = kt * 16 + tq * 2;
        W2f[i * 2 + 0] = pack2h(W2[ks * 64 + n], W2[(ks + 1) * 64 + n]);
        W2f[i * 2 + 1] = pack2h(W2[(ks + 8) * 64 + n], W2[(ks + 9) * 64 + n]);
    }
    for (int i = tid; i < 4 * 24 * 32; i += 256) {
        int lane = i & 31, nt = (i >> 5) % 24, kt = i / (24 * 32);
        int gq = lane >> 2, tq = lane & 3;
        int gcol = nt * 8 + gq, ks = kt * 16 + tq * 2;
        Wihf[i * 2 + 0] = pack2h(Wih[gcol * 64 + ks], Wih[gcol * 64 + ks + 1]);
        Wihf[i * 2 + 1] = pack2h(Wih[gcol * 64 + ks + 8], Wih[gcol * 64 + ks + 9]);
        Whhf[i * 2 + 0] = pack2h(Whh[gcol * 64 + ks], Whh[gcol * 64 + ks + 1]);
        Whhf[i * 2 + 1] = pack2h(Whh[gcol * 64 + ks + 8], Whh[gcol * 64 + ks + 9]);
    }
    for (int i = tid; i < 4 * 4 * 32; i += 256) {
        int lane = i & 31, nt = (i >> 5) & 3, kt = i >> 7;
        int gq = lane >> 2, tq = lane & 3;
        int n = nt * 8 + gq, ks = kt * 16 + tq * 2;
        Wc1f[i * 2 + 0] = pack2h(Wc1[ks * 32 + n], Wc1[(ks + 1) * 32 + n]);
        Wc1f[i * 2 + 1] = pack2h(Wc1[(ks + 8) * 32 + n], Wc1[(ks + 9) * 32 + n]);
    }
    for (int i = tid; i < 8 * 32; i += 256) {
        int lane = i & 31, nt = i >> 5, tq = lane & 3;
        B2f[i] = make_float2(b2[nt * 8 + tq * 2], b2[nt * 8 + tq * 2 + 1]);
        Bin[i] = make_float2(bih[128 + nt * 8 + tq * 2], bih[128 + nt * 8 + tq * 2 + 1]);
        Bhn[i] = make_float2(bhh[128 + nt * 8 + tq * 2], bhh[128 + nt * 8 + tq * 2 + 1]);
    }
    for (int i = tid; i < 16 * 32; i += 256) {
        int lane = i & 31, nt = i >> 5, tq = lane & 3;
        int k0 = nt * 8 + tq * 2;
        Brz[i] = make_float2(bih[k0] + bhh[k0], bih[k0 + 1] + bhh[k0 + 1]);
    }
    for (int i = tid; i < 4 * 32; i += 256) {
        int lane = i & 31, nt = i >> 5, tq = lane & 3;
        Bc1f[i] = make_float2(bc1[nt * 8 + tq * 2], bc1[nt * 8 + tq * 2 + 1]);
    }
    if (tid < 32) w2s[tid] = Wc2[tid];
    __syncthreads();

    int lane = tid & 31;
    int tile = blockIdx.x * 8 + (tid >> 5);
    if (tile >= NN / 16) return;
    int row0 = tile * 16;
    int gq = lane >> 2, tq = lane & 3;

    float hc[8][4];
    #pragma unroll
    for (int nt = 0; nt < 8; nt++)
        #pragma unroll
        for (int j = 0; j < 4; j++) hc[nt][j] = 0.f;

    for (int t = 0; t < TT; t++) {
        float dall[24][4];
        #pragma unroll
        for (int nt = 0; nt < 16; nt++) {
            float2 bb = Brz[nt * 32 + lane];
            dall[nt][0] = bb.x; dall[nt][1] = bb.y; dall[nt][2] = bb.x; dall[nt][3] = bb.y;
        }
        #pragma unroll
        for (int nt = 0; nt < 8; nt++) {
            float2 bb = Bhn[nt * 32 + lane];
            dall[16 + nt][0] = bb.x; dall[16 + nt][1] = bb.y;
            dall[16 + nt][2] = bb.x; dall[16 + nt][3] = bb.y;
        }
        if (t) {
            unsigned int Ah[4][4];
            #pragma unroll
            for (int kt = 0; kt < 4; kt++) {
                Ah[kt][0] = pack2h(hc[2 * kt][0], hc[2 * kt][1]);
                Ah[kt][1] = pack2h(hc[2 * kt][2], hc[2 * kt][3]);
                Ah[kt][2] = pack2h(hc[2 * kt + 1][0], hc[2 * kt + 1][1]);
                Ah[kt][3] = pack2h(hc[2 * kt + 1][2], hc[2 * kt + 1][3]);
            }
            #pragma unroll
            for (int kt = 0; kt < 4; kt++)
                #pragma unroll
                for (int nt = 0; nt < 24; nt++)
                    mma16816(dall[nt], Ah[kt], &Whhf[((kt * 24 + nt) * 32 + lane) * 2]);
        }
        unsigned int A[4][4];
        {
            const unsigned int* base0 = (const unsigned int*)(P2H + ((size_t)t * NN + row0 + gq) * 64);
            const unsigned int* base8 = base0 + 8 * 32;
            #pragma unroll
            for (int kt = 0; kt < 4; kt++) {
                A[kt][0] = base0[kt * 8 + tq];
                A[kt][1] = base8[kt * 8 + tq];
                A[kt][2] = base0[kt * 8 + tq + 4];
                A[kt][3] = base8[kt * 8 + tq + 4];
            }
        }
        float c[8][4];
        #pragma unroll
        for (int nt = 0; nt < 8; nt++) {
            float2 bb = B2f[nt * 32 + lane];
            c[nt][0] = bb.x; c[nt][1] = bb.y; c[nt][2] = bb.x; c[nt][3] = bb.y;
        }
        #pragma unroll
        for (int kt = 0; kt < 4; kt++)
            #pragma unroll
            for (int nt = 0; nt < 8; nt++)
                mma16816(c[nt], A[kt], &W2f[((kt * 8 + nt) * 32 + lane) * 2]);
        unsigned int A2[4][4];
        #pragma unroll
        for (int kt = 0; kt < 4; kt++) {
            A2[kt][0] = pack2h(fmaxf(c[2 * kt][0], 0.f), fmaxf(c[2 * kt][1], 0.f));
            A2[kt][1] = pack2h(fmaxf(c[2 * kt][2], 0.f), fmaxf(c[2 * kt][3], 0.f));
            A2[kt][2] = pack2h(fmaxf(c[2 * kt + 1][0], 0.f), fmaxf(c[2 * kt + 1][1], 0.f));
            A2[kt][3] = pack2h(fmaxf(c[2 * kt + 1][2], 0.f), fmaxf(c[2 * kt + 1][3], 0.f));
        }
        #pragma unroll
        for (int kt = 0; kt < 4; kt++)
            #pragma unroll
            for (int nt = 0; nt < 16; nt++)
                mma16816(dall[nt], A2[kt], &Wihf[((kt * 24 + nt) * 32 + lane) * 2]);
        float din[8][4];
        #pragma unroll
        for (int nt = 0; nt < 8; nt++) {
            float2 bb = Bin[nt * 32 + lane];
            din[nt][0] = bb.x; din[nt][1] = bb.y; din[nt][2] = bb.x; din[nt][3] = bb.y;
        }
        #pragma unroll
        for (int kt = 0; kt < 4; kt++)
            #pragma unroll
            for (int nt = 0; nt < 8; nt++)
                mma16816(din[nt], A2[kt], &Wihf[((kt * 24 + 16 + nt) * 32 + lane) * 2]);
        #pragma unroll
        for (int nt = 0; nt < 8; nt++) {
            #pragma unroll
            for (int j = 0; j < 4; j++) {
                float r = sigf(dall[nt][j]);
                float z = sigf(dall[nt + 8][j]);
                float n = tanhf_fast(din[nt][j] + r * dall[nt + 16][j]);
                hc[nt][j] = (1.f - z) * n + z * hc[nt][j];
            }
        }
    }

    // ---- classifier
    unsigned int Ah[4][4];
    #pragma unroll
    for (int kt = 0; kt < 4; kt++) {
        Ah[kt][0] = pack2h(hc[2 * kt][0], hc[2 * kt][1]);
        Ah[kt][1] = pack2h(hc[2 * kt][2], hc[2 * kt][3]);
        Ah[kt][2] = pack2h(hc[2 * kt + 1][0], hc[2 * kt + 1][1]);
        Ah[kt][3] = pack2h(hc[2 * kt + 1][2], hc[2 * kt + 1][3]);
    }
    float hid[4][4];
    #pragma unroll
    for (int nt = 0; nt < 4; nt++) {
        float2 bb = Bc1f[nt * 32 + lane];
        hid[nt][0] = bb.x; hid[nt][1] = bb.y; hid[nt][2] = bb.x; hid[nt][3] = bb.y;
    }
    #pragma unroll
    for (int kt = 0; kt < 4; kt++)
        #pragma unroll
        for (int nt = 0; nt < 4; nt++)
            mma16816(hid[nt], Ah[kt], &Wc1f[((kt * 4 + nt) * 32 + lane) * 2]);
    float p0 = 0.f, p8 = 0.f;
    #pragma unroll
    for (int nt = 0; nt < 4; nt++) {
        float w0 = w2s[nt * 8 + tq * 2], w1 = w2s[nt * 8 + tq * 2 + 1];
        p0 += fmaxf(hid[nt][0], 0.f) * w0 + fmaxf(hid[nt][1], 0.f) * w1;
        p8 += fmaxf(hid[nt][2], 0.f) * w0 + fmaxf(hid[nt][3], 0.f) * w1;
    }
    p0 += __shfl_xor_sync(0xffffffffu, p0, 1);
    p0 += __shfl_xor_sync(0xffffffffu, p0, 2);
    p8 += __shfl_xor_sync(0xffffffffu, p8, 1);
    p8 += __shfl_xor_sync(0xffffffffu, p8, 2);
    if (tq == 0) {
        float bv = bc2[0];
        out[row0 + gq] = p0 + bv;
        out[row0 + gq + 8] = p8 + bv;
    }
}

// ---------------- launch ----------------------------------------------------
extern "C" void kernel_launch(void* const* d_in, const int* in_sizes, int n_in,
                              void* d_out, int out_size) {
    const float* x   = (const float*)d_in[0];
    const int*   ei  = (const int*)d_in[1];
    const float* W1  = (const float*)d_in[2];
    const float* b1  = (const float*)d_in[3];
    const float* W2  = (const float*)d_in[4];
    const float* b2  = (const float*)d_in[5];
    const float* Wih = (const float*)d_in[6];
    const float* Whh = (const float*)d_in[7];
    const float* bih = (const float*)d_in[8];
    const float* bhh = (const float*)d_in[9];
    const float* Wc1 = (const float*)d_in[10];
    const float* bc1 = (const float*)d_in[11];
    const float* Wc2 = (const float*)d_in[12];
    const float* bc2 = (const float*)d_in[13];
    float* out = (float*)d_out;

    int E = in_sizes[1] / 2;
    const int* src = ei;
    const int* dst = ei + E;

    cudaFuncSetAttribute(k_fused, cudaFuncAttributeMaxDynamicSharedMemorySize, 73728);

    // preprocessing: count+cvt, fused scan, CSR fill
    k_countcvt<<<(ROWS * FF / 4 + 255) / 256, 256>>>(dst, E, (const float4*)x);
    k_pre12<<<NB, 1024>>>();
    k_fill<<<((E + 1) / 2 + 255) / 256, 256>>>(src, dst, E);

    // layer 1: P1 = Ahat * x (3 t-chunks, warp-per-node) -> fp16 P1H
    k_agg32<<<dim3(NN / 8, 3), 256>>>();
    // h1 = relu(P1 @ W1 + b1) via HMMA -> fp16 H1H
    k_gemm1h<<<(ROWS / 16 + 7) / 8, 256>>>(W1, b1);

    // layer 2: P2 = Ahat * h1 (6 chunks of 2 t) -> fp16 P2H
    k_agg64<<<dim3(NN / 8, 6), 256>>>();

    // fused HMMA: h2 + gi + 12-step GRU + classifier -> out
    k_fused<<<(NN / 16 + 7) / 8, 256, 73728>>>(W2, b2, Wih, bih, Whh, bhh,
                                               Wc1, bc1, Wc2, bc2, out);
}

// round 14
// speedup vs baseline: 1.1455x; 1.0826x over previous
#include <cuda_runtime.h>
#include <cuda_fp16.h>
#include <math.h>

// Problem constants
constexpr int TT = 12;
constexpr int NN = 50000;
constexpr int FF = 32;
constexpr int HH = 64;
constexpr int EE = 1600000;
constexpr int ROWS = TT * NN;     // 600000
constexpr int NB = (NN + 1023) / 1024;   // 49 scan blocks

// ---------------- static device scratch (zero-initialized at load) ---------
__device__ int     g_degi[NN];
__device__ int     g_cursor[NN];
__device__ float   g_dinv[NN];
__device__ float   g_invdeg[NN];
__device__ int     g_rowptr[NN + 1];     // local (per-scan-block) prefix
__device__ int     g_bsum[64];
__device__ int     g_boff[64];
__device__ unsigned int g_epku[EE];                        // packed src:16 | w:fp16
__device__ uint4   g_xhu4[(size_t)ROWS * FF / 8];          // 38.4 MB x fp16
__device__ uint4   g_p1u4[(size_t)ROWS * FF / 8];          // 38.4 MB P1 fp16
__device__ uint4   g_h1u4[(size_t)ROWS * HH / 8];          // 76.8 MB h1 fp16
__device__ uint4   g_p2u4[(size_t)ROWS * HH / 8];          // 76.8 MB P2 fp16

#define P1H  ((__half*)g_p1u4)
#define H1H  ((__half*)g_h1u4)
#define P2H  ((__half*)g_p2u4)

// ---------------- helpers ---------------------------------------------------
union F2U { float2 f; unsigned long long u; };
__device__ __forceinline__ float2 ffma2(float2 a, float2 b, float2 c) {
    F2U A, B, C, D; A.f = a; B.f = b; C.f = c;
    asm("fma.rn.f32x2 %0, %1, %2, %3;" : "=l"(D.u) : "l"(A.u), "l"(B.u), "l"(C.u));
    return D.f;
}
__device__ __forceinline__ float2 h2f2(unsigned int u) {
    __half2 h = *reinterpret_cast<const __half2*>(&u);
    return __half22float2(h);
}
__device__ __forceinline__ unsigned int pack2h(float a, float b) {
    __half2 h = __floats2half2_rn(a, b);
    return *reinterpret_cast<unsigned int*>(&h);
}
__device__ __forceinline__ float sigf(float x) { return 1.f / (1.f + expf(-x)); }

// m16n8k16 fp16 MMA, fp32 accumulate (A row-major, B col-major)
__device__ __forceinline__ void mma16816(float* c, const unsigned int* a, const unsigned int* b) {
    asm volatile(
        "mma.sync.aligned.m16n8k16.row.col.f32.f16.f16.f32 "
        "{%0,%1,%2,%3}, {%4,%5,%6,%7}, {%8,%9}, {%0,%1,%2,%3};\n"
        : "+f"(c[0]), "+f"(c[1]), "+f"(c[2]), "+f"(c[3])
        : "r"(a[0]), "r"(a[1]), "r"(a[2]), "r"(a[3]), "r"(b[0]), "r"(b[1]));
}

// ---------------- preprocessing --------------------------------------------
__global__ __launch_bounds__(256) void k_countcvt(const int* __restrict__ dst, int E,
                                                  const float4* __restrict__ x4) {
    unsigned int i = blockIdx.x * blockDim.x + threadIdx.x;
    if (i < (unsigned int)E) atomicAdd(&g_degi[dst[i]], 1);
    if (i < (unsigned int)(ROWS * FF / 4)) {
        float4 v = x4[i];
        ((uint2*)g_xhu4)[i] = make_uint2(pack2h(v.x, v.y), pack2h(v.z, v.w));
    }
}

__global__ void k_pre1() {
    __shared__ int wsum[32];
    int b = blockIdx.x, tid = threadIdx.x, lane = tid & 31, wid = tid >> 5;
    int idx = b * 1024 + tid;
    int v = (idx < NN) ? g_degi[idx] : 0;
    int x = v;
    #pragma unroll
    for (int o = 1; o < 32; o <<= 1) {
        int y = __shfl_up_sync(0xffffffffu, x, o);
        if (lane >= o) x += y;
    }
    if (lane == 31) wsum[wid] = x;
    __syncthreads();
    if (wid == 0) {
        int w = wsum[lane];
        int xw = w;
        #pragma unroll
        for (int o = 1; o < 32; o <<= 1) {
            int y = __shfl_up_sync(0xffffffffu, xw, o);
            if (lane >= o) xw += y;
        }
        wsum[lane] = xw - w;
    }
    __syncthreads();
    int excl = wsum[wid] + x - v;
    if (idx < NN) {
        g_rowptr[idx] = excl;
        float deg = (float)v + 1.0f;
        g_dinv[idx] = rsqrtf(deg);
        g_invdeg[idx] = 1.0f / deg;
    }
    if (tid == 1023) g_bsum[b] = excl + v;
}

__global__ void k_pre2() {
    int l = threadIdx.x;   // 32 threads
    int a = (l < NB) ? g_bsum[l] : 0;
    int xa = a;
    #pragma unroll
    for (int o = 1; o < 32; o <<= 1) {
        int y = __shfl_up_sync(0xffffffffu, xa, o);
        if (l >= o) xa += y;
    }
    int totalA = __shfl_sync(0xffffffffu, xa, 31);
    int b2 = (l + 32 < NB) ? g_bsum[l + 32] : 0;
    int xb = b2;
    #pragma unroll
    for (int o = 1; o < 32; o <<= 1) {
        int y = __shfl_up_sync(0xffffffffu, xb, o);
        if (l >= o) xb += y;
    }
    g_boff[l] = xa - a;
    if (l + 32 < NB + 1) g_boff[l + 32] = totalA + xb - b2;
    if (l == 0) g_rowptr[NN] = g_bsum[NB - 1];
}

__global__ void k_fill(const int* __restrict__ src, const int* __restrict__ dst, int E) {
    int e = blockIdx.x * blockDim.x + threadIdx.x;
    if (e < E) {
        int s = src[e], d = dst[e];
        float w = g_dinv[s] * g_dinv[d];
        int pos = g_rowptr[d] + g_boff[d >> 10] + atomicAdd(&g_cursor[d], 1);
        unsigned short ws = __half_as_ushort(__float2half_rn(w));
        g_epku[pos] = (unsigned int)s | ((unsigned int)ws << 16);
    }
}

__device__ __forceinline__ void decode_edge(unsigned int e, int& ss, float& ww) {
    ss = (int)(e & 0xFFFFu);
    ww = __half2float(__ushort_as_half((unsigned short)(e >> 16)));
}

// ---------------- aggregation layer 1: warp-per-node, fp16 gather -----------
__global__ __launch_bounds__(256) void k_agg32() {
    int lane = threadIdx.x & 31;
    int n = blockIdx.x * 8 + (threadIdx.x >> 5);
    if (n >= NN) return;
    int c = blockIdx.y;                                  // 0..2
    int g = lane >> 2, sub = lane & 3;
    const uint4* __restrict__ x4 = g_xhu4 + (size_t)(c * 4) * NN * 4 + sub;
    int r0 = g_rowptr[n] + g_boff[n >> 10];
    int r1 = g_rowptr[n + 1] + g_boff[(n + 1) >> 10];
    float2 acc[4][4];
    #pragma unroll
    for (int t = 0; t < 4; t++)
        #pragma unroll
        for (int j = 0; j < 4; j++) acc[t][j] = make_float2(0.f, 0.f);
    unsigned int ep = (r0 + lane < r1) ? g_epku[r0 + lane] : 0u;
    for (int tile = r0; tile < r1; tile += 32) {
        unsigned int epc = ep;
        int nxt = tile + 32;
        if (nxt < r1) ep = (nxt + lane < r1) ? g_epku[nxt + lane] : 0u;
        int nb = r1 - tile; if (nb > 32) nb = 32;
        for (int b = 0; b * 8 < nb; b++) {
            unsigned int e = __shfl_sync(0xffffffffu, epc, b * 8 + g);
            int ss; float ww; decode_edge(e, ss, ww);
            float2 w2 = make_float2(ww, ww);
            const uint4* p = x4 + (size_t)ss * 4;
            #pragma unroll
            for (int t = 0; t < 4; t++) {
                uint4 v = p[(size_t)t * (NN * 4)];
                acc[t][0] = ffma2(w2, h2f2(v.x), acc[t][0]);
                acc[t][1] = ffma2(w2, h2f2(v.y), acc[t][1]);
                acc[t][2] = ffma2(w2, h2f2(v.z), acc[t][2]);
                acc[t][3] = ffma2(w2, h2f2(v.w), acc[t][3]);
            }
        }
    }
    if (g == 0) {   // self-loop, added once pre-reduction
        float id = g_invdeg[n];
        float2 w2 = make_float2(id, id);
        const uint4* p = x4 + (size_t)n * 4;
        #pragma unroll
        for (int t = 0; t < 4; t++) {
            uint4 v = p[(size_t)t * (NN * 4)];
            acc[t][0] = ffma2(w2, h2f2(v.x), acc[t][0]);
            acc[t][1] = ffma2(w2, h2f2(v.y), acc[t][1]);
            acc[t][2] = ffma2(w2, h2f2(v.z), acc[t][2]);
            acc[t][3] = ffma2(w2, h2f2(v.w), acc[t][3]);
        }
    }
    #pragma unroll
    for (int t = 0; t < 4; t++) {
        #pragma unroll
        for (int j = 0; j < 4; j++) {
            float2 a = acc[t][j];
            #pragma unroll
            for (int off = 4; off <= 16; off <<= 1) {
                a.x += __shfl_xor_sync(0xffffffffu, a.x, off);
                a.y += __shfl_xor_sync(0xffffffffu, a.y, off);
            }
            acc[t][j] = a;
        }
        if (g == t) {
            uint4 pk;
            pk.x = pack2h(acc[t][0].x, acc[t][0].y);
            pk.y = pack2h(acc[t][1].x, acc[t][1].y);
            pk.z = pack2h(acc[t][2].x, acc[t][2].y);
            pk.w = pack2h(acc[t][3].x, acc[t][3].y);
            g_p1u4[((size_t)(c * 4 + t) * NN + n) * 4 + sub] = pk;
        }
    }
}

// ---------------- HMMA dense layer 1: h1 = relu(P1 @ W1 + b1) -> fp16 -------
__global__ __launch_bounds__(256) void k_gemm1h(const float* __restrict__ W,
                                                const float* __restrict__ b) {
    __shared__ unsigned int Wf[2 * 8 * 32 * 2];   // 4 KB
    __shared__ float2 Bf[8 * 32];                 // 2 KB
    int tid = threadIdx.x;
    for (int i = tid; i < 2 * 8 * 32; i += 256) {
        int lane = i & 31, nt = (i >> 5) & 7, kt = i >> 8;
        int gq = lane >> 2, tq = lane & 3;
        int n = nt * 8 + gq, ks = kt * 16 + tq * 2;
        Wf[i * 2 + 0] = pack2h(W[ks * 64 + n], W[(ks + 1) * 64 + n]);
        Wf[i * 2 + 1] = pack2h(W[(ks + 8) * 64 + n], W[(ks + 9) * 64 + n]);
    }
    for (int i = tid; i < 8 * 32; i += 256) {
        int lane = i & 31, nt = i >> 5, tq = lane & 3;
        Bf[i] = make_float2(b[nt * 8 + tq * 2], b[nt * 8 + tq * 2 + 1]);
    }
    __syncthreads();
    int lane = tid & 31;
    int tile = blockIdx.x * 8 + (tid >> 5);
    if (tile >= ROWS / 16) return;
    int row0 = tile * 16;
    int gq = lane >> 2, tq = lane & 3;

    unsigned int A[2][4];
    const unsigned int* base0 = (const unsigned int*)(P1H + (size_t)(row0 + gq) * 32);
    const unsigned int* base8 = (const unsigned int*)(P1H + (size_t)(row0 + gq + 8) * 32);
    #pragma unroll
    for (int kt = 0; kt < 2; kt++) {
        A[kt][0] = base0[kt * 8 + tq];
        A[kt][1] = base8[kt * 8 + tq];
        A[kt][2] = base0[kt * 8 + tq + 4];
        A[kt][3] = base8[kt * 8 + tq + 4];
    }
    float c[8][4];
    #pragma unroll
    for (int nt = 0; nt < 8; nt++) {
        float2 bb = Bf[nt * 32 + lane];
        c[nt][0] = bb.x; c[nt][1] = bb.y; c[nt][2] = bb.x; c[nt][3] = bb.y;
    }
    #pragma unroll
    for (int kt = 0; kt < 2; kt++)
        #pragma unroll
        for (int nt = 0; nt < 8; nt++)
            mma16816(c[nt], A[kt], &Wf[((kt * 8 + nt) * 32 + lane) * 2]);
    unsigned int* o0 = (unsigned int*)(H1H + (size_t)(row0 + gq) * 64);
    unsigned int* o8 = (unsigned int*)(H1H + (size_t)(row0 + gq + 8) * 64);
    #pragma unroll
    for (int nt = 0; nt < 8; nt++) {
        o0[nt * 4 + tq] = pack2h(fmaxf(c[nt][0], 0.f), fmaxf(c[nt][1], 0.f));
        o8[nt * 4 + tq] = pack2h(fmaxf(c[nt][2], 0.f), fmaxf(c[nt][3], 0.f));
    }
}

// ---------------- aggregation layer 2: fp16 in/out, 2 t per slice -----------
__global__ __launch_bounds__(256) void k_agg64() {
    int lane = threadIdx.x & 31;
    int n = blockIdx.x * 8 + (threadIdx.x >> 5);
    if (n >= NN) return;
    int c = blockIdx.y;                                  // 0..5
    int g = lane >> 3, sub = lane & 7;
    int r0 = g_rowptr[n] + g_boff[n >> 10];
    int r1 = g_rowptr[n + 1] + g_boff[(n + 1) >> 10];
    const uint4* __restrict__ hb = g_h1u4 + (size_t)(c * 2) * NN * 8 + sub;
    float2 acc[2][4];
    #pragma unroll
    for (int t = 0; t < 2; t++)
        #pragma unroll
        for (int j = 0; j < 4; j++) acc[t][j] = make_float2(0.f, 0.f);
    unsigned int ep = (r0 + lane < r1) ? g_epku[r0 + lane] : 0u;
    for (int tile = r0; tile < r1; tile += 32) {
        unsigned int epc = ep;
        int nxt = tile + 32;
        if (nxt < r1) ep = (nxt + lane < r1) ? g_epku[nxt + lane] : 0u;
        int nb = r1 - tile; if (nb > 32) nb = 32;
        for (int b = 0; b * 4 < nb; b++) {
            unsigned int e = __shfl_sync(0xffffffffu, epc, b * 4 + g);
            int ss; float ww; decode_edge(e, ss, ww);
            float2 w2 = make_float2(ww, ww);
            const uint4* p = hb + (size_t)ss * 8;
            #pragma unroll
            for (int t = 0; t < 2; t++) {
                uint4 hv = p[(size_t)t * (NN * 8)];
                acc[t][0] = ffma2(w2, h2f2(hv.x), acc[t][0]);
                acc[t][1] = ffma2(w2, h2f2(hv.y), acc[t][1]);
                acc[t][2] = ffma2(w2, h2f2(hv.z), acc[t][2]);
                acc[t][3] = ffma2(w2, h2f2(hv.w), acc[t][3]);
            }
        }
    }
    if (g == 0) {
        float id = g_invdeg[n];
        float2 w2 = make_float2(id, id);
        const uint4* p = hb + (size_t)n * 8;
        #pragma unroll
        for (int t = 0; t < 2; t++) {
            uint4 hv = p[(size_t)t * (NN * 8)];
            acc[t][0] = ffma2(w2, h2f2(hv.x), acc[t][0]);
            acc[t][1] = ffma2(w2, h2f2(hv.y), acc[t][1]);
            acc[t][2] = ffma2(w2, h2f2(hv.z), acc[t][2]);
            acc[t][3] = ffma2(w2, h2f2(hv.w), acc[t][3]);
        }
    }
    #pragma unroll
    for (int t = 0; t < 2; t++) {
        #pragma unroll
        for (int j = 0; j < 4; j++) {
            float2 a = acc[t][j];
            #pragma unroll
            for (int off = 8; off <= 16; off <<= 1) {
                a.x += __shfl_xor_sync(0xffffffffu, a.x, off);
                a.y += __shfl_xor_sync(0xffffffffu, a.y, off);
            }
            acc[t][j] = a;
        }
        if (g == t) {
            uint4 pk;
            pk.x = pack2h(acc[t][0].x, acc[t][0].y);
            pk.y = pack2h(acc[t][1].x, acc[t][1].y);
            pk.z = pack2h(acc[t][2].x, acc[t][2].y);
            pk.w = pack2h(acc[t][3].x, acc[t][3].y);
            g_p2u4[((size_t)(c * 2 + t) * NN + n) * 8 + sub] = pk;
        }
    }
}

// ---------------- fused HMMA: h2+gi+GRU+classifier --------------------------
__global__ __launch_bounds__(256) void k_fused(const float* __restrict__ W2,
                                               const float* __restrict__ b2,
                                               const float* __restrict__ Wih,
                                               const float* __restrict__ bih,
                                               const float* __restrict__ Whh,
                                               const float* __restrict__ bhh,
                                               const float* __restrict__ Wc1,
                                               const float* __restrict__ bc1,
                                               const float* __restrict__ Wc2,
                                               const float* __restrict__ bc2,
                                               float* __restrict__ out) {
    extern __shared__ unsigned int smu[];
    unsigned int* W2f  = smu;                  // [0,2048)
    unsigned int* Wihf = smu + 2048;           // [2048,8192)
    unsigned int* Whhf = smu + 8192;           // [8192,14336)
    float2* B2f = (float2*)(smu + 14336);      // [14336,14848)
    float2* Brz = (float2*)(smu + 14848);      // [14848,15872)
    float2* Bin = (float2*)(smu + 15872);      // [15872,16384)
    float2* Bhn = (float2*)(smu + 16384);      // [16384,16896)
    unsigned int* Wc1f = smu + 16896;          // [16896,17920)
    float2* Bc1f = (float2*)(smu + 17920);     // [17920,18176)
    float* w2s = (float*)(smu + 18176);        // [18176,18208)
    int tid = threadIdx.x;

    int gid = blockIdx.x * 256 + tid;
    if (gid < NN) { g_degi[gid] = 0; g_cursor[gid] = 0; }

    for (int i = tid; i < 4 * 8 * 32; i += 256) {
        int lane = i & 31, nt = (i >> 5) & 7, kt = i >> 8;
        int gq = lane >> 2, tq = lane & 3;
        int n = nt * 8 + gq, ks = kt * 16 + tq * 2;
        W2f[i * 2 + 0] = pack2h(W2[ks * 64 + n], W2[(ks + 1) * 64 + n]);
        W2f[i * 2 + 1] = pack2h(W2[(ks + 8) * 64 + n], W2[(ks + 9) * 64 + n]);
    }
    for (int i = tid; i < 4 * 24 * 32; i += 256) {
        int lane = i & 31, nt = (i >> 5) % 24, kt = i / (24 * 32);
        int gq = lane >> 2, tq = lane & 3;
        int gcol = nt * 8 + gq, ks = kt * 16 + tq * 2;
        Wihf[i * 2 + 0] = pack2h(Wih[gcol * 64 + ks], Wih[gcol * 64 + ks + 1]);
        Wihf[i * 2 + 1] = pack2h(Wih[gcol * 64 + ks + 8], Wih[gcol * 64 + ks + 9]);
        Whhf[i * 2 + 0] = pack2h(Whh[gcol * 64 + ks], Whh[gcol * 64 + ks + 1]);
        Whhf[i * 2 + 1] = pack2h(Whh[gcol * 64 + ks + 8], Whh[gcol * 64 + ks + 9]);
    }
    for (int i = tid; i < 4 * 4 * 32; i += 256) {
        int lane = i & 31, nt = (i >> 5) & 3, kt = i >> 7;
        int gq = lane >> 2, tq = lane & 3;
        int n = nt * 8 + gq, ks = kt * 16 + tq * 2;
        Wc1f[i * 2 + 0] = pack2h(Wc1[ks * 32 + n], Wc1[(ks + 1) * 32 + n]);
        Wc1f[i * 2 + 1] = pack2h(Wc1[(ks + 8) * 32 + n], Wc1[(ks + 9) * 32 + n]);
    }
    for (int i = tid; i < 8 * 32; i += 256) {
        int lane = i & 31, nt = i >> 5, tq = lane & 3;
        B2f[i] = make_float2(b2[nt * 8 + tq * 2], b2[nt * 8 + tq * 2 + 1]);
        Bin[i] = make_float2(bih[128 + nt * 8 + tq * 2], bih[128 + nt * 8 + tq * 2 + 1]);
        Bhn[i] = make_float2(bhh[128 + nt * 8 + tq * 2], bhh[128 + nt * 8 + tq * 2 + 1]);
    }
    for (int i = tid; i < 16 * 32; i += 256) {
        int lane = i & 31, nt = i >> 5, tq = lane & 3;
        int k0 = nt * 8 + tq * 2;
        Brz[i] = make_float2(bih[k0] + bhh[k0], bih[k0 + 1] + bhh[k0 + 1]);
    }
    for (int i = tid; i < 4 * 32; i += 256) {
        int lane = i & 31, nt = i >> 5, tq = lane & 3;
        Bc1f[i] = make_float2(bc1[nt * 8 + tq * 2], bc1[nt * 8 + tq * 2 + 1]);
    }
    if (tid < 32) w2s[tid] = Wc2[tid];
    __syncthreads();

    int lane = tid & 31;
    int tile = blockIdx.x * 8 + (tid >> 5);
    if (tile >= NN / 16) return;
    int row0 = tile * 16;
    int gq = lane >> 2, tq = lane & 3;

    float hc[8][4];
    #pragma unroll
    for (int nt = 0; nt < 8; nt++)
        #pragma unroll
        for (int j = 0; j < 4; j++) hc[nt][j] = 0.f;

    for (int t = 0; t < TT; t++) {
        float dall[24][4];
        #pragma unroll
        for (int nt = 0; nt < 16; nt++) {
            float2 bb = Brz[nt * 32 + lane];
            dall[nt][0] = bb.x; dall[nt][1] = bb.y; dall[nt][2] = bb.x; dall[nt][3] = bb.y;
        }
        #pragma unroll
        for (int nt = 0; nt < 8; nt++) {
            float2 bb = Bhn[nt * 32 + lane];
            dall[16 + nt][0] = bb.x; dall[16 + nt][1] = bb.y;
            dall[16 + nt][2] = bb.x; dall[16 + nt][3] = bb.y;
        }
        if (t) {
            unsigned int Ah[4][4];
            #pragma unroll
            for (int kt = 0; kt < 4; kt++) {
                Ah[kt][0] = pack2h(hc[2 * kt][0], hc[2 * kt][1]);
                Ah[kt][1] = pack2h(hc[2 * kt][2], hc[2 * kt][3]);
                Ah[kt][2] = pack2h(hc[2 * kt + 1][0], hc[2 * kt + 1][1]);
                Ah[kt][3] = pack2h(hc[2 * kt + 1][2], hc[2 * kt + 1][3]);
            }
            #pragma unroll
            for (int kt = 0; kt < 4; kt++)
                #pragma unroll
                for (int nt = 0; nt < 24; nt++)
                    mma16816(dall[nt], Ah[kt], &Whhf[((kt * 24 + nt) * 32 + lane) * 2]);
        }
        unsigned int A[4][4];
        {
            const unsigned int* base0 = (const unsigned int*)(P2H + ((size_t)t * NN + row0 + gq) * 64);
            const unsigned int* base8 = base0 + 8 * 32;
            #pragma unroll
            for (int kt = 0; kt < 4; kt++) {
                A[kt][0] = base0[kt * 8 + tq];
                A[kt][1] = base8[kt * 8 + tq];
                A[kt][2] = base0[kt * 8 + tq + 4];
                A[kt][3] = base8[kt * 8 + tq + 4];
            }
        }
        float c[8][4];
        #pragma unroll
        for (int nt = 0; nt < 8; nt++) {
            float2 bb = B2f[nt * 32 + lane];
            c[nt][0] = bb.x; c[nt][1] = bb.y; c[nt][2] = bb.x; c[nt][3] = bb.y;
        }
        #pragma unroll
        for (int kt = 0; kt < 4; kt++)
            #pragma unroll
            for (int nt = 0; nt < 8; nt++)
                mma16816(c[nt], A[kt], &W2f[((kt * 8 + nt) * 32 + lane) * 2]);
        unsigned int A2[4][4];
        #pragma unroll
        for (int kt = 0; kt < 4; kt++) {
            A2[kt][0] = pack2h(fmaxf(c[2 * kt][0], 0.f), fmaxf(c[2 * kt][1], 0.f));
            A2[kt][1] = pack2h(fmaxf(c[2 * kt][2], 0.f), fmaxf(c[2 * kt][3], 0.f));
            A2[kt][2] = pack2h(fmaxf(c[2 * kt + 1][0], 0.f), fmaxf(c[2 * kt + 1][1], 0.f));
            A2[kt][3] = pack2h(fmaxf(c[2 * kt + 1][2], 0.f), fmaxf(c[2 * kt + 1][3], 0.f));
        }
        #pragma unroll
        for (int kt = 0; kt < 4; kt++)
            #pragma unroll
            for (int nt = 0; nt < 16; nt++)
                mma16816(dall[nt], A2[kt], &Wihf[((kt * 24 + nt) * 32 + lane) * 2]);
        float din[8][4];
        #pragma unroll
        for (int nt = 0; nt < 8; nt++) {
            float2 bb = Bin[nt * 32 + lane];
            din[nt][0] = bb.x; din[nt][1] = bb.y; din[nt][2] = bb.x; din[nt][3] = bb.y;
        }
        #pragma unroll
        for (int kt = 0; kt < 4; kt++)
            #pragma unroll
            for (int nt = 0; nt < 8; nt++)
                mma16816(din[nt], A2[kt], &Wihf[((kt * 24 + 16 + nt) * 32 + lane) * 2]);
        #pragma unroll
        for (int nt = 0; nt < 8; nt++) {
            #pragma unroll
            for (int j = 0; j < 4; j++) {
                float r = sigf(dall[nt][j]);
                float z = sigf(dall[nt + 8][j]);
                float n = tanhf(din[nt][j] + r * dall[nt + 16][j]);
                hc[nt][j] = (1.f - z) * n + z * hc[nt][j];
            }
        }
    }

    // ---- classifier
    unsigned int Ah[4][4];
    #pragma unroll
    for (int kt = 0; kt < 4; kt++) {
        Ah[kt][0] = pack2h(hc[2 * kt][0], hc[2 * kt][1]);
        Ah[kt][1] = pack2h(hc[2 * kt][2], hc[2 * kt][3]);
        Ah[kt][2] = pack2h(hc[2 * kt + 1][0], hc[2 * kt + 1][1]);
        Ah[kt][3] = pack2h(hc[2 * kt + 1][2], hc[2 * kt + 1][3]);
    }
    float hid[4][4];
    #pragma unroll
    for (int nt = 0; nt < 4; nt++) {
        float2 bb = Bc1f[nt * 32 + lane];
        hid[nt][0] = bb.x; hid[nt][1] = bb.y; hid[nt][2] = bb.x; hid[nt][3] = bb.y;
    }
    #pragma unroll
    for (int kt = 0; kt < 4; kt++)
        #pragma unroll
        for (int nt = 0; nt < 4; nt++)
            mma16816(hid[nt], Ah[kt], &Wc1f[((kt * 4 + nt) * 32 + lane) * 2]);
    float p0 = 0.f, p8 = 0.f;
    #pragma unroll
    for (int nt = 0; nt < 4; nt++) {
        float w0 = w2s[nt * 8 + tq * 2], w1 = w2s[nt * 8 + tq * 2 + 1];
        p0 += fmaxf(hid[nt][0], 0.f) * w0 + fmaxf(hid[nt][1], 0.f) * w1;
        p8 += fmaxf(hid[nt][2], 0.f) * w0 + fmaxf(hid[nt][3], 0.f) * w1;
    }
    p0 += __shfl_xor_sync(0xffffffffu, p0, 1);
    p0 += __shfl_xor_sync(0xffffffffu, p0, 2);
    p8 += __shfl_xor_sync(0xffffffffu, p8, 1);
    p8 += __shfl_xor_sync(0xffffffffu, p8, 2);
    if (tq == 0) {
        float bv = bc2[0];
        out[row0 + gq] = p0 + bv;
        out[row0 + gq + 8] = p8 + bv;
    }
}

// ---------------- launch ----------------------------------------------------
extern "C" void kernel_launch(void* const* d_in, const int* in_sizes, int n_in,
                              void* d_out, int out_size) {
    const float* x   = (const float*)d_in[0];
    const int*   ei  = (const int*)d_in[1];
    const float* W1  = (const float*)d_in[2];
    const float* b1  = (const float*)d_in[3];
    const float* W2  = (const float*)d_in[4];
    const float* b2  = (const float*)d_in[5];
    const float* Wih = (const float*)d_in[6];
    const float* Whh = (const float*)d_in[7];
    const float* bih = (const float*)d_in[8];
    const float* bhh = (const float*)d_in[9];
    const float* Wc1 = (const float*)d_in[10];
    const float* bc1 = (const float*)d_in[11];
    const float* Wc2 = (const float*)d_in[12];
    const float* bc2 = (const float*)d_in[13];
    float* out = (float*)d_out;

    int E = in_sizes[1] / 2;
    const int* src = ei;
    const int* dst = ei + E;

    cudaFuncSetAttribute(k_fused, cudaFuncAttributeMaxDynamicSharedMemorySize, 73728);

    // preprocessing: count+cvt, scan (2 stages), CSR fill
    k_countcvt<<<(ROWS * FF / 4 + 255) / 256, 256>>>(dst, E, (const float4*)x);
    k_pre1<<<NB, 1024>>>();
    k_pre2<<<1, 32>>>();
    k_fill<<<(E + 255) / 256, 256>>>(src, dst, E);

    // layer 1: P1 = Ahat * x (3 t-chunks, warp-per-node) -> fp16 P1H
    k_agg32<<<dim3(NN / 8, 3), 256>>>();
    // h1 = relu(P1 @ W1 + b1) via HMMA -> fp16 H1H
    k_gemm1h<<<(ROWS / 16 + 7) / 8, 256>>>(W1, b1);

    // layer 2: P2 = Ahat * h1 (6 chunks of 2 t) -> fp16 P2H
    k_agg64<<<dim3(NN / 8, 6), 256>>>();

    // fused HMMA: h2 + gi + 12-step GRU + classifier -> out
    k_fused<<<(NN / 16 + 7) / 8, 256, 73728>>>(W2, b2, Wih, bih, Whh, bhh,
                                               Wc1, bc1, Wc2, bc2, out);
}

// round 15
// speedup vs baseline: 1.3716x; 1.1973x over previous
#include <cuda_runtime.h>
#include <cuda_fp16.h>
#include <math.h>

// Problem constants
constexpr int TT = 12;
constexpr int NN = 50000;
constexpr int FF = 32;
constexpr int HH = 64;
constexpr int EE = 1600000;
constexpr int ROWS = TT * NN;     // 600000
constexpr int NB = (NN + 1023) / 1024;   // 49 scan blocks

// ---------------- static device scratch (zero-initialized at load) ---------
__device__ int     g_degi[NN];
__device__ int     g_cursor[NN];
__device__ float   g_dinv[NN];
__device__ float   g_invdeg[NN];
__device__ int     g_rowptr[NN + 1];     // local (per-scan-block) prefix
__device__ int     g_bsum[64];
__device__ int     g_boff[64];
__device__ unsigned int g_epku[EE];                        // packed src:16 | w:fp16
__device__ uint4   g_xhu4[(size_t)ROWS * FF / 8];          // 38.4 MB x fp16
__device__ uint4   g_p1u4[(size_t)ROWS * FF / 8];          // 38.4 MB P1 fp16
__device__ uint4   g_h1u4[(size_t)ROWS * HH / 8];          // 76.8 MB h1 fp16
__device__ uint4   g_p2u4[(size_t)ROWS * HH / 8];          // 76.8 MB P2 fp16

#define P1H  ((__half*)g_p1u4)
#define H1H  ((__half*)g_h1u4)
#define P2H  ((__half*)g_p2u4)

// ---------------- helpers ---------------------------------------------------
union F2U { float2 f; unsigned long long u; };
__device__ __forceinline__ float2 ffma2(float2 a, float2 b, float2 c) {
    F2U A, B, C, D; A.f = a; B.f = b; C.f = c;
    asm("fma.rn.f32x2 %0, %1, %2, %3;" : "=l"(D.u) : "l"(A.u), "l"(B.u), "l"(C.u));
    return D.f;
}
__device__ __forceinline__ float2 h2f2(unsigned int u) {
    __half2 h = *reinterpret_cast<const __half2*>(&u);
    return __half22float2(h);
}
__device__ __forceinline__ unsigned int pack2h(float a, float b) {
    __half2 h = __floats2half2_rn(a, b);
    return *reinterpret_cast<unsigned int*>(&h);
}
// fast activations: MUFU-based (__expf = EX2, __fdividef = RCP), rel err ~1e-6
__device__ __forceinline__ float sigf(float x) {
    return __fdividef(1.f, 1.f + __expf(-x));
}
__device__ __forceinline__ float tanhf_fast(float x) {
    float t = __expf(-2.f * fabsf(x));
    float r = (1.f - t) * __fdividef(1.f, 1.f + t);
    return copysignf(r, x);
}

// m16n8k16 fp16 MMA, fp32 accumulate (A row-major, B col-major)
__device__ __forceinline__ void mma16816(float* c, const unsigned int* a, const unsigned int* b) {
    asm volatile(
        "mma.sync.aligned.m16n8k16.row.col.f32.f16.f16.f32 "
        "{%0,%1,%2,%3}, {%4,%5,%6,%7}, {%8,%9}, {%0,%1,%2,%3};\n"
        : "+f"(c[0]), "+f"(c[1]), "+f"(c[2]), "+f"(c[3])
        : "r"(a[0]), "r"(a[1]), "r"(a[2]), "r"(a[3]), "r"(b[0]), "r"(b[1]));
}

// ---------------- preprocessing --------------------------------------------
__global__ __launch_bounds__(256) void k_countcvt(const int* __restrict__ dst, int E,
                                                  const float4* __restrict__ x4) {
    unsigned int i = blockIdx.x * blockDim.x + threadIdx.x;
    if (i < (unsigned int)E) atomicAdd(&g_degi[dst[i]], 1);
    if (i < (unsigned int)(ROWS * FF / 4)) {
        float4 v = x4[i];
        ((uint2*)g_xhu4)[i] = make_uint2(pack2h(v.x, v.y), pack2h(v.z, v.w));
    }
}

__global__ void k_pre1() {
    __shared__ int wsum[32];
    int b = blockIdx.x, tid = threadIdx.x, lane = tid & 31, wid = tid >> 5;
    int idx = b * 1024 + tid;
    int v = (idx < NN) ? g_degi[idx] : 0;
    int x = v;
    #pragma unroll
    for (int o = 1; o < 32; o <<= 1) {
        int y = __shfl_up_sync(0xffffffffu, x, o);
        if (lane >= o) x += y;
    }
    if (lane == 31) wsum[wid] = x;
    __syncthreads();
    if (wid == 0) {
        int w = wsum[lane];
        int xw = w;
        #pragma unroll
        for (int o = 1; o < 32; o <<= 1) {
            int y = __shfl_up_sync(0xffffffffu, xw, o);
            if (lane >= o) xw += y;
        }
        wsum[lane] = xw - w;
    }
    __syncthreads();
    int excl = wsum[wid] + x - v;
    if (idx < NN) {
        g_rowptr[idx] = excl;
        float deg = (float)v + 1.0f;
        g_dinv[idx] = rsqrtf(deg);
        g_invdeg[idx] = 1.0f / deg;
    }
    if (tid == 1023) g_bsum[b] = excl + v;
}

__global__ void k_pre2() {
    int l = threadIdx.x;   // 32 threads
    int a = (l < NB) ? g_bsum[l] : 0;
    int xa = a;
    #pragma unroll
    for (int o = 1; o < 32; o <<= 1) {
        int y = __shfl_up_sync(0xffffffffu, xa, o);
        if (l >= o) xa += y;
    }
    int totalA = __shfl_sync(0xffffffffu, xa, 31);
    int b2 = (l + 32 < NB) ? g_bsum[l + 32] : 0;
    int xb = b2;
    #pragma unroll
    for (int o = 1; o < 32; o <<= 1) {
        int y = __shfl_up_sync(0xffffffffu, xb, o);
        if (l >= o) xb += y;
    }
    g_boff[l] = xa - a;
    if (l + 32 < NB + 1) g_boff[l + 32] = totalA + xb - b2;
    if (l == 0) g_rowptr[NN] = g_bsum[NB - 1];
}

__global__ void k_fill(const int* __restrict__ src, const int* __restrict__ dst, int E) {
    int e = blockIdx.x * blockDim.x + threadIdx.x;
    if (e < E) {
        int s = src[e], d = dst[e];
        float w = g_dinv[s] * g_dinv[d];
        int pos = g_rowptr[d] + g_boff[d >> 10] + atomicAdd(&g_cursor[d], 1);
        unsigned short ws = __half_as_ushort(__float2half_rn(w));
        g_epku[pos] = (unsigned int)s | ((unsigned int)ws << 16);
    }
}

__device__ __forceinline__ void decode_edge(unsigned int e, int& ss, float& ww) {
    ss = (int)(e & 0xFFFFu);
    ww = __half2float(__ushort_as_half((unsigned short)(e >> 16)));
}

// ---------------- aggregation layer 1: warp-per-node, fp16 gather -----------
__global__ __launch_bounds__(256) void k_agg32() {
    int lane = threadIdx.x & 31;
    int n = blockIdx.x * 8 + (threadIdx.x >> 5);
    if (n >= NN) return;
    int c = blockIdx.y;                                  // 0..2
    int g = lane >> 2, sub = lane & 3;
    const uint4* __restrict__ x4 = g_xhu4 + (size_t)(c * 4) * NN * 4 + sub;
    int r0 = g_rowptr[n] + g_boff[n >> 10];
    int r1 = g_rowptr[n + 1] + g_boff[(n + 1) >> 10];
    float2 acc[4][4];
    #pragma unroll
    for (int t = 0; t < 4; t++)
        #pragma unroll
        for (int j = 0; j < 4; j++) acc[t][j] = make_float2(0.f, 0.f);
    unsigned int ep = (r0 + lane < r1) ? g_epku[r0 + lane] : 0u;
    for (int tile = r0; tile < r1; tile += 32) {
        unsigned int epc = ep;
        int nxt = tile + 32;
        if (nxt < r1) ep = (nxt + lane < r1) ? g_epku[nxt + lane] : 0u;
        int nb = r1 - tile; if (nb > 32) nb = 32;
        for (int b = 0; b * 8 < nb; b++) {
            unsigned int e = __shfl_sync(0xffffffffu, epc, b * 8 + g);
            int ss; float ww; decode_edge(e, ss, ww);
            float2 w2 = make_float2(ww, ww);
            const uint4* p = x4 + (size_t)ss * 4;
            #pragma unroll
            for (int t = 0; t < 4; t++) {
                uint4 v = p[(size_t)t * (NN * 4)];
                acc[t][0] = ffma2(w2, h2f2(v.x), acc[t][0]);
                acc[t][1] = ffma2(w2, h2f2(v.y), acc[t][1]);
                acc[t][2] = ffma2(w2, h2f2(v.z), acc[t][2]);
                acc[t][3] = ffma2(w2, h2f2(v.w), acc[t][3]);
            }
        }
    }
    if (g == 0) {   // self-loop, added once pre-reduction
        float id = g_invdeg[n];
        float2 w2 = make_float2(id, id);
        const uint4* p = x4 + (size_t)n * 4;
        #pragma unroll
        for (int t = 0; t < 4; t++) {
            uint4 v = p[(size_t)t * (NN * 4)];
            acc[t][0] = ffma2(w2, h2f2(v.x), acc[t][0]);
            acc[t][1] = ffma2(w2, h2f2(v.y), acc[t][1]);
            acc[t][2] = ffma2(w2, h2f2(v.z), acc[t][2]);
            acc[t][3] = ffma2(w2, h2f2(v.w), acc[t][3]);
        }
    }
    #pragma unroll
    for (int t = 0; t < 4; t++) {
        #pragma unroll
        for (int j = 0; j < 4; j++) {
            float2 a = acc[t][j];
            #pragma unroll
            for (int off = 4; off <= 16; off <<= 1) {
                a.x += __shfl_xor_sync(0xffffffffu, a.x, off);
                a.y += __shfl_xor_sync(0xffffffffu, a.y, off);
            }
            acc[t][j] = a;
        }
        if (g == t) {
            uint4 pk;
            pk.x = pack2h(acc[t][0].x, acc[t][0].y);
            pk.y = pack2h(acc[t][1].x, acc[t][1].y);
            pk.z = pack2h(acc[t][2].x, acc[t][2].y);
            pk.w = pack2h(acc[t][3].x, acc[t][3].y);
            g_p1u4[((size_t)(c * 4 + t) * NN + n) * 4 + sub] = pk;
        }
    }
}

// ---------------- HMMA dense layer 1: h1 = relu(P1 @ W1 + b1) -> fp16 -------
__global__ __launch_bounds__(256) void k_gemm1h(const float* __restrict__ W,
                                                const float* __restrict__ b) {
    __shared__ unsigned int Wf[2 * 8 * 32 * 2];   // 4 KB
    __shared__ float2 Bf[8 * 32];                 // 2 KB
    int tid = threadIdx.x;
    for (int i = tid; i < 2 * 8 * 32; i += 256) {
        int lane = i & 31, nt = (i >> 5) & 7, kt = i >> 8;
        int gq = lane >> 2, tq = lane & 3;
        int n = nt * 8 + gq, ks = kt * 16 + tq * 2;
        Wf[i * 2 + 0] = pack2h(W[ks * 64 + n], W[(ks + 1) * 64 + n]);
        Wf[i * 2 + 1] = pack2h(W[(ks + 8) * 64 + n], W[(ks + 9) * 64 + n]);
    }
    for (int i = tid; i < 8 * 32; i += 256) {
        int lane = i & 31, nt = i >> 5, tq = lane & 3;
        Bf[i] = make_float2(b[nt * 8 + tq * 2], b[nt * 8 + tq * 2 + 1]);
    }
    __syncthreads();
    int lane = tid & 31;
    int tile = blockIdx.x * 8 + (tid >> 5);
    if (tile >= ROWS / 16) return;
    int row0 = tile * 16;
    int gq = lane >> 2, tq = lane & 3;

    unsigned int A[2][4];
    const unsigned int* base0 = (const unsigned int*)(P1H + (size_t)(row0 + gq) * 32);
    const unsigned int* base8 = (const unsigned int*)(P1H + (size_t)(row0 + gq + 8) * 32);
    #pragma unroll
    for (int kt = 0; kt < 2; kt++) {
        A[kt][0] = base0[kt * 8 + tq];
        A[kt][1] = base8[kt * 8 + tq];
        A[kt][2] = base0[kt * 8 + tq + 4];
        A[kt][3] = base8[kt * 8 + tq + 4];
    }
    float c[8][4];
    #pragma unroll
    for (int nt = 0; nt < 8; nt++) {
        float2 bb = Bf[nt * 32 + lane];
        c[nt][0] = bb.x; c[nt][1] = bb.y; c[nt][2] = bb.x; c[nt][3] = bb.y;
    }
    #pragma unroll
    for (int kt = 0; kt < 2; kt++)
        #pragma unroll
        for (int nt = 0; nt < 8; nt++)
            mma16816(c[nt], A[kt], &Wf[((kt * 8 + nt) * 32 + lane) * 2]);
    unsigned int* o0 = (unsigned int*)(H1H + (size_t)(row0 + gq) * 64);
    unsigned int* o8 = (unsigned int*)(H1H + (size_t)(row0 + gq + 8) * 64);
    #pragma unroll
    for (int nt = 0; nt < 8; nt++) {
        o0[nt * 4 + tq] = pack2h(fmaxf(c[nt][0], 0.f), fmaxf(c[nt][1], 0.f));
        o8[nt * 4 + tq] = pack2h(fmaxf(c[nt][2], 0.f), fmaxf(c[nt][3], 0.f));
    }
}

// ---------------- aggregation layer 2: fp16 in/out, 2 t per slice -----------
__global__ __launch_bounds__(256) void k_agg64() {
    int lane = threadIdx.x & 31;
    int n = blockIdx.x * 8 + (threadIdx.x >> 5);
    if (n >= NN) return;
    int c = blockIdx.y;                                  // 0..5
    int g = lane >> 3, sub = lane & 7;
    int r0 = g_rowptr[n] + g_boff[n >> 10];
    int r1 = g_rowptr[n + 1] + g_boff[(n + 1) >> 10];
    const uint4* __restrict__ hb = g_h1u4 + (size_t)(c * 2) * NN * 8 + sub;
    float2 acc[2][4];
    #pragma unroll
    for (int t = 0; t < 2; t++)
        #pragma unroll
        for (int j = 0; j < 4; j++) acc[t][j] = make_float2(0.f, 0.f);
    unsigned int ep = (r0 + lane < r1) ? g_epku[r0 + lane] : 0u;
    for (int tile = r0; tile < r1; tile += 32) {
        unsigned int epc = ep;
        int nxt = tile + 32;
        if (nxt < r1) ep = (nxt + lane < r1) ? g_epku[nxt + lane] : 0u;
        int nb = r1 - tile; if (nb > 32) nb = 32;
        for (int b = 0; b * 4 < nb; b++) {
            unsigned int e = __shfl_sync(0xffffffffu, epc, b * 4 + g);
            int ss; float ww; decode_edge(e, ss, ww);
            float2 w2 = make_float2(ww, ww);
            const uint4* p = hb + (size_t)ss * 8;
            #pragma unroll
            for (int t = 0; t < 2; t++) {
                uint4 hv = p[(size_t)t * (NN * 8)];
                acc[t][0] = ffma2(w2, h2f2(hv.x), acc[t][0]);
                acc[t][1] = ffma2(w2, h2f2(hv.y), acc[t][1]);
                acc[t][2] = ffma2(w2, h2f2(hv.z), acc[t][2]);
                acc[t][3] = ffma2(w2, h2f2(hv.w), acc[t][3]);
            }
        }
    }
    if (g == 0) {
        float id = g_invdeg[n];
        float2 w2 = make_float2(id, id);
        const uint4* p = hb + (size_t)n * 8;
        #pragma unroll
        for (int t = 0; t < 2; t++) {
            uint4 hv = p[(size_t)t * (NN * 8)];
            acc[t][0] = ffma2(w2, h2f2(hv.x), acc[t][0]);
            acc[t][1] = ffma2(w2, h2f2(hv.y), acc[t][1]);
            acc[t][2] = ffma2(w2, h2f2(hv.z), acc[t][2]);
            acc[t][3] = ffma2(w2, h2f2(hv.w), acc[t][3]);
        }
    }
    #pragma unroll
    for (int t = 0; t < 2; t++) {
        #pragma unroll
        for (int j = 0; j < 4; j++) {
            float2 a = acc[t][j];
            #pragma unroll
            for (int off = 8; off <= 16; off <<= 1) {
                a.x += __shfl_xor_sync(0xffffffffu, a.x, off);
                a.y += __shfl_xor_sync(0xffffffffu, a.y, off);
            }
            acc[t][j] = a;
        }
        if (g == t) {
            uint4 pk;
            pk.x = pack2h(acc[t][0].x, acc[t][0].y);
            pk.y = pack2h(acc[t][1].x, acc[t][1].y);
            pk.z = pack2h(acc[t][2].x, acc[t][2].y);
            pk.w = pack2h(acc[t][3].x, acc[t][3].y);
            g_p2u4[((size_t)(c * 2 + t) * NN + n) * 8 + sub] = pk;
        }
    }
}

// ---------------- fused HMMA: h2+gi+GRU+classifier --------------------------
__global__ __launch_bounds__(256) void k_fused(const float* __restrict__ W2,
                                               const float* __restrict__ b2,
                                               const float* __restrict__ Wih,
                                               const float* __restrict__ bih,
                                               const float* __restrict__ Whh,
                                               const float* __restrict__ bhh,
                                               const float* __restrict__ Wc1,
                                               const float* __restrict__ bc1,
                                               const float* __restrict__ Wc2,
                                               const float* __restrict__ bc2,
                                               float* __restrict__ out) {
    extern __shared__ unsigned int smu[];
    unsigned int* W2f  = smu;                  // [0,2048)
    unsigned int* Wihf = smu + 2048;           // [2048,8192)
    unsigned int* Whhf = smu + 8192;           // [8192,14336)
    float2* B2f = (float2*)(smu + 14336);      // [14336,14848)
    float2* Brz = (float2*)(smu + 14848);      // [14848,15872)
    float2* Bin = (float2*)(smu + 15872);      // [15872,16384)
    float2* Bhn = (float2*)(smu + 16384);      // [16384,16896)
    unsigned int* Wc1f = smu + 16896;          // [16896,17920)
    float2* Bc1f = (float2*)(smu + 17920);     // [17920,18176)
    float* w2s = (float*)(smu + 18176);        // [18176,18208)
    int tid = threadIdx.x;

    int gid = blockIdx.x * 256 + tid;
    if (gid < NN) { g_degi[gid] = 0; g_cursor[gid] = 0; }

    for (int i = tid; i < 4 * 8 * 32; i += 256) {
        int lane = i & 31, nt = (i >> 5) & 7, kt = i >> 8;
        int gq = lane >> 2, tq = lane & 3;
        int n = nt * 8 + gq, ks = kt * 16 + tq * 2;
        W2f[i * 2 + 0] = pack2h(W2[ks * 64 + n], W2[(ks + 1) * 64 + n]);
        W2f[i * 2 + 1] = pack2h(W2[(ks + 8) * 64 + n], W2[(ks + 9) * 64 + n]);
    }
    for (int i = tid; i < 4 * 24 * 32; i += 256) {
        int lane = i & 31, nt = (i >> 5) % 24, kt = i / (24 * 32);
        int gq = lane >> 2, tq = lane & 3;
        int gcol = nt * 8 + gq, ks = kt * 16 + tq * 2;
        Wihf[i * 2 + 0] = pack2h(Wih[gcol * 64 + ks], Wih[gcol * 64 + ks + 1]);
        Wihf[i * 2 + 1] = pack2h(Wih[gcol * 64 + ks + 8], Wih[gcol * 64 + ks + 9]);
        Whhf[i * 2 + 0] = pack2h(Whh[gcol * 64 + ks], Whh[gcol * 64 + ks + 1]);
        Whhf[i * 2 + 1] = pack2h(Whh[gcol * 64 + ks + 8], Whh[gcol * 64 + ks + 9]);
    }
    for (int i = tid; i < 4 * 4 * 32; i += 256) {
        int lane = i & 31, nt = (i >> 5) & 3, kt = i >> 7;
        int gq = lane >> 2, tq = lane & 3;
        int n = nt * 8 + gq, ks = kt * 16 + tq * 2;
        Wc1f[i * 2 + 0] = pack2h(Wc1[ks * 32 + n], Wc1[(ks + 1) * 32 + n]);
        Wc1f[i * 2 + 1] = pack2h(Wc1[(ks + 8) * 32 + n], Wc1[(ks + 9) * 32 + n]);
    }
    for (int i = tid; i < 8 * 32; i += 256) {
        int lane = i & 31, nt = i >> 5, tq = lane & 3;
        B2f[i] = make_float2(b2[nt * 8 + tq * 2], b2[nt * 8 + tq * 2 + 1]);
        Bin[i] = make_float2(bih[128 + nt * 8 + tq * 2], bih[128 + nt * 8 + tq * 2 + 1]);
        Bhn[i] = make_float2(bhh[128 + nt * 8 + tq * 2], bhh[128 + nt * 8 + tq * 2 + 1]);
    }
    for (int i = tid; i < 16 * 32; i += 256) {
        int lane = i & 31, nt = i >> 5, tq = lane & 3;
        int k0 = nt * 8 + tq * 2;
        Brz[i] = make_float2(bih[k0] + bhh[k0], bih[k0 + 1] + bhh[k0 + 1]);
    }
    for (int i = tid; i < 4 * 32; i += 256) {
        int lane = i & 31, nt = i >> 5, tq = lane & 3;
        Bc1f[i] = make_float2(bc1[nt * 8 + tq * 2], bc1[nt * 8 + tq * 2 + 1]);
    }
    if (tid < 32) w2s[tid] = Wc2[tid];
    __syncthreads();

    int lane = tid & 31;
    int tile = blockIdx.x * 8 + (tid >> 5);
    if (tile >= NN / 16) return;
    int row0 = tile * 16;
    int gq = lane >> 2, tq = lane & 3;

    float hc[8][4];
    #pragma unroll
    for (int nt = 0; nt < 8; nt++)
        #pragma unroll
        for (int j = 0; j < 4; j++) hc[nt][j] = 0.f;

    for (int t = 0; t < TT; t++) {
        float dall[24][4];
        #pragma unroll
        for (int nt = 0; nt < 16; nt++) {
            float2 bb = Brz[nt * 32 + lane];
            dall[nt][0] = bb.x; dall[nt][1] = bb.y; dall[nt][2] = bb.x; dall[nt][3] = bb.y;
        }
        #pragma unroll
        for (int nt = 0; nt < 8; nt++) {
            float2 bb = Bhn[nt * 32 + lane];
            dall[16 + nt][0] = bb.x; dall[16 + nt][1] = bb.y;
            dall[16 + nt][2] = bb.x; dall[16 + nt][3] = bb.y;
        }
        if (t) {
            unsigned int Ah[4][4];
            #pragma unroll
            for (int kt = 0; kt < 4; kt++) {
                Ah[kt][0] = pack2h(hc[2 * kt][0], hc[2 * kt][1]);
                Ah[kt][1] = pack2h(hc[2 * kt][2], hc[2 * kt][3]);
                Ah[kt][2] = pack2h(hc[2 * kt + 1][0], hc[2 * kt + 1][1]);
                Ah[kt][3] = pack2h(hc[2 * kt + 1][2], hc[2 * kt + 1][3]);
            }
            #pragma unroll
            for (int kt = 0; kt < 4; kt++)
                #pragma unroll
                for (int nt = 0; nt < 24; nt++)
                    mma16816(dall[nt], Ah[kt], &Whhf[((kt * 24 + nt) * 32 + lane) * 2]);
        }
        unsigned int A[4][4];
        {
            const unsigned int* base0 = (const unsigned int*)(P2H + ((size_t)t * NN + row0 + gq) * 64);
            const unsigned int* base8 = base0 + 8 * 32;
            #pragma unroll
            for (int kt = 0; kt < 4; kt++) {
                A[kt][0] = base0[kt * 8 + tq];
                A[kt][1] = base8[kt * 8 + tq];
                A[kt][2] = base0[kt * 8 + tq + 4];
                A[kt][3] = base8[kt * 8 + tq + 4];
            }
        }
        float c[8][4];
        #pragma unroll
        for (int nt = 0; nt < 8; nt++) {
            float2 bb = B2f[nt * 32 + lane];
            c[nt][0] = bb.x; c[nt][1] = bb.y; c[nt][2] = bb.x; c[nt][3] = bb.y;
        }
        #pragma unroll
        for (int kt = 0; kt < 4; kt++)
            #pragma unroll
            for (int nt = 0; nt < 8; nt++)
                mma16816(c[nt], A[kt], &W2f[((kt * 8 + nt) * 32 + lane) * 2]);
        unsigned int A2[4][4];
        #pragma unroll
        for (int kt = 0; kt < 4; kt++) {
            A2[kt][0] = pack2h(fmaxf(c[2 * kt][0], 0.f), fmaxf(c[2 * kt][1], 0.f));
            A2[kt][1] = pack2h(fmaxf(c[2 * kt][2], 0.f), fmaxf(c[2 * kt][3], 0.f));
            A2[kt][2] = pack2h(fmaxf(c[2 * kt + 1][0], 0.f), fmaxf(c[2 * kt + 1][1], 0.f));
            A2[kt][3] = pack2h(fmaxf(c[2 * kt + 1][2], 0.f), fmaxf(c[2 * kt + 1][3], 0.f));
        }
        #pragma unroll
        for (int kt = 0; kt < 4; kt++)
            #pragma unroll
            for (int nt = 0; nt < 16; nt++)
                mma16816(dall[nt], A2[kt], &Wihf[((kt * 24 + nt) * 32 + lane) * 2]);
        float din[8][4];
        #pragma unroll
        for (int nt = 0; nt < 8; nt++) {
            float2 bb = Bin[nt * 32 + lane];
            din[nt][0] = bb.x; din[nt][1] = bb.y; din[nt][2] = bb.x; din[nt][3] = bb.y;
        }
        #pragma unroll
        for (int kt = 0; kt < 4; kt++)
            #pragma unroll
            for (int nt = 0; nt < 8; nt++)
                mma16816(din[nt], A2[kt], &Wihf[((kt * 24 + 16 + nt) * 32 + lane) * 2]);
        #pragma unroll
        for (int nt = 0; nt < 8; nt++) {
            #pragma unroll
            for (int j = 0; j < 4; j++) {
                float r = sigf(dall[nt][j]);
                float z = sigf(dall[nt + 8][j]);
                float n = tanhf_fast(din[nt][j] + r * dall[nt + 16][j]);
                hc[nt][j] = (1.f - z) * n + z * hc[nt][j];
            }
        }
    }

    // ---- classifier
    unsigned int Ah[4][4];
    #pragma unroll
    for (int kt = 0; kt < 4; kt++) {
        Ah[kt][0] = pack2h(hc[2 * kt][0], hc[2 * kt][1]);
        Ah[kt][1] = pack2h(hc[2 * kt][2], hc[2 * kt][3]);
        Ah[kt][2] = pack2h(hc[2 * kt + 1][0], hc[2 * kt + 1][1]);
        Ah[kt][3] = pack2h(hc[2 * kt + 1][2], hc[2 * kt + 1][3]);
    }
    float hid[4][4];
    #pragma unroll
    for (int nt = 0; nt < 4; nt++) {
        float2 bb = Bc1f[nt * 32 + lane];
        hid[nt][0] = bb.x; hid[nt][1] = bb.y; hid[nt][2] = bb.x; hid[nt][3] = bb.y;
    }
    #pragma unroll
    for (int kt = 0; kt < 4; kt++)
        #pragma unroll
        for (int nt = 0; nt < 4; nt++)
            mma16816(hid[nt], Ah[kt], &Wc1f[((kt * 4 + nt) * 32 + lane) * 2]);
    float p0 = 0.f, p8 = 0.f;
    #pragma unroll
    for (int nt = 0; nt < 4; nt++) {
        float w0 = w2s[nt * 8 + tq * 2], w1 = w2s[nt * 8 + tq * 2 + 1];
        p0 += fmaxf(hid[nt][0], 0.f) * w0 + fmaxf(hid[nt][1], 0.f) * w1;
        p8 += fmaxf(hid[nt][2], 0.f) * w0 + fmaxf(hid[nt][3], 0.f) * w1;
    }
    p0 += __shfl_xor_sync(0xffffffffu, p0, 1);
    p0 += __shfl_xor_sync(0xffffffffu, p0, 2);
    p8 += __shfl_xor_sync(0xffffffffu, p8, 1);
    p8 += __shfl_xor_sync(0xffffffffu, p8, 2);
    if (tq == 0) {
        float bv = bc2[0];
        out[row0 + gq] = p0 + bv;
        out[row0 + gq + 8] = p8 + bv;
    }
}

// ---------------- launch ----------------------------------------------------
extern "C" void kernel_launch(void* const* d_in, const int* in_sizes, int n_in,
                              void* d_out, int out_size) {
    const float* x   = (const float*)d_in[0];
    const int*   ei  = (const int*)d_in[1];
    const float* W1  = (const float*)d_in[2];
    const float* b1  = (const float*)d_in[3];
    const float* W2  = (const float*)d_in[4];
    const float* b2  = (const float*)d_in[5];
    const float* Wih = (const float*)d_in[6];
    const float* Whh = (const float*)d_in[7];
    const float* bih = (const float*)d_in[8];
    const float* bhh = (const float*)d_in[9];
    const float* Wc1 = (const float*)d_in[10];
    const float* bc1 = (const float*)d_in[11];
    const float* Wc2 = (const float*)d_in[12];
    const float* bc2 = (const float*)d_in[13];
    float* out = (float*)d_out;

    int E = in_sizes[1] / 2;
    const int* src = ei;
    const int* dst = ei + E;

    cudaFuncSetAttribute(k_fused, cudaFuncAttributeMaxDynamicSharedMemorySize, 73728);

    // preprocessing: count+cvt, scan (2 stages), CSR fill
    k_countcvt<<<(ROWS * FF / 4 + 255) / 256, 256>>>(dst, E, (const float4*)x);
    k_pre1<<<NB, 1024>>>();
    k_pre2<<<1, 32>>>();
    k_fill<<<(E + 255) / 256, 256>>>(src, dst, E);

    // layer 1: P1 = Ahat * x (3 t-chunks, warp-per-node) -> fp16 P1H
    k_agg32<<<dim3(NN / 8, 3), 256>>>();
    // h1 = relu(P1 @ W1 + b1) via HMMA -> fp16 H1H
    k_gemm1h<<<(ROWS / 16 + 7) / 8, 256>>>(W1, b1);

    // layer 2: P2 = Ahat * h1 (6 chunks of 2 t) -> fp16 P2H
    k_agg64<<<dim3(NN / 8, 6), 256>>>();

    // fused HMMA: h2 + gi + 12-step GRU + classifier -> out
    k_fused<<<(NN / 16 + 7) / 8, 256, 73728>>>(W2, b2, Wih, bih, Whh, bhh,
                                               Wc1, bc1, Wc2, bc2, out);
}